// round 1
// baseline (speedup 1.0000x reference)
#include <cuda_runtime.h>

#define BATCH 2
#define SEQ   2048
#define EMB   1024
#define NH    16
#define HD    64
#define M_TOT (BATCH*SEQ)   // 4096
#define N_TOT (3*EMB)       // 3072
#define K_TOT EMB           // 1024

#define BQ 64
#define BK 64
#define SP 68  // padded smem stride (keeps float4 16B alignment: 68*4=272=16*17)

// Scratch for Q/K/V in [B, H, T, D] layout (device globals: allocation-free)
__device__ float g_q[(size_t)BATCH*NH*SEQ*HD];
__device__ float g_k[(size_t)BATCH*NH*SEQ*HD];
__device__ float g_v[(size_t)BATCH*NH*SEQ*HD];

// ---------------------------------------------------------------------------
// Kernel 1: QKV = X @ W + b, scattered into g_q/g_k/g_v as [B,H,T,D]
// 128x128 block tile, k-tile 16, 256 threads, 8x8 per-thread microtile.
// ---------------------------------------------------------------------------
__global__ __launch_bounds__(256) void qkv_gemm(const float* __restrict__ X,
                                                const float* __restrict__ W,
                                                const float* __restrict__ bias) {
    __shared__ float As[16][128];   // transposed: As[k][m]
    __shared__ float Bs[16][128];   // Bs[k][n]

    const int bm = blockIdx.y;
    const int bn = blockIdx.x;
    const int tid = threadIdx.x;
    const int ty = tid >> 4;        // 0..15 -> rows ty*8..+8
    const int tx = tid & 15;        // 0..15 -> cols tx*8..+8

    float acc[8][8];
    #pragma unroll
    for (int i = 0; i < 8; i++)
        #pragma unroll
        for (int j = 0; j < 8; j++) acc[i][j] = 0.f;

    for (int kk = 0; kk < K_TOT; kk += 16) {
        // Load A tile (128 rows x 16 k), store transposed
        #pragma unroll
        for (int i = 0; i < 2; i++) {
            int f = tid * 2 + i;           // 0..511 float4 slots
            int row = f >> 2;              // 0..127
            int kc  = (f & 3) << 2;        // 0,4,8,12
            float4 a4 = *(const float4*)(X + (size_t)(bm * 128 + row) * K_TOT + kk + kc);
            As[kc + 0][row] = a4.x;
            As[kc + 1][row] = a4.y;
            As[kc + 2][row] = a4.z;
            As[kc + 3][row] = a4.w;
        }
        // Load B tile (16 k x 128 n)
        #pragma unroll
        for (int i = 0; i < 2; i++) {
            int f = tid * 2 + i;
            int row = f >> 5;              // 0..15
            int nc  = (f & 31) << 2;       // 0..124
            *(float4*)(&Bs[row][nc]) =
                *(const float4*)(W + (size_t)(kk + row) * N_TOT + bn * 128 + nc);
        }
        __syncthreads();

        #pragma unroll
        for (int k = 0; k < 16; k++) {
            float ra[8], rb[8];
            *(float4*)(ra)     = *(float4*)(&As[k][ty * 8]);
            *(float4*)(ra + 4) = *(float4*)(&As[k][ty * 8 + 4]);
            *(float4*)(rb)     = *(float4*)(&Bs[k][tx * 8]);
            *(float4*)(rb + 4) = *(float4*)(&Bs[k][tx * 8 + 4]);
            #pragma unroll
            for (int i = 0; i < 8; i++)
                #pragma unroll
                for (int j = 0; j < 8; j++)
                    acc[i][j] += ra[i] * rb[j];
        }
        __syncthreads();
    }

    // Epilogue: add bias, scatter to [B,H,T,D]
    #pragma unroll
    for (int i = 0; i < 8; i++) {
        int m = bm * 128 + ty * 8 + i;
        int b = m / SEQ, t = m % SEQ;
        #pragma unroll
        for (int j = 0; j < 8; j++) {
            int n = bn * 128 + tx * 8 + j;
            float v = acc[i][j] + bias[n];
            int p = n / EMB, c = n % EMB;
            int h = c / HD,  d = c % HD;
            size_t idx = ((size_t)(b * NH + h) * SEQ + t) * HD + d;
            float* dst = (p == 0) ? g_q : (p == 1) ? g_k : g_v;
            dst[idx] = v;
        }
    }
}

// ---------------------------------------------------------------------------
// Kernel 2: flash-attention (causal, online softmax).
// One block per (b, h, 64-row Q tile); 256 threads; 4x4 register microtiles.
// smem: Qs[d][r], Ks[d][j] (transposed, stride 68), Vs[j][d], Ps[r][j].
// ---------------------------------------------------------------------------
__global__ __launch_bounds__(256) void attn_kernel(float* __restrict__ out) {
    extern __shared__ float sm[];
    float (*Qs)[SP] = (float(*)[SP])(sm);                       // HD x SP
    float (*Ks)[SP] = (float(*)[SP])(sm + HD * SP);             // HD x SP
    float (*Vs)[HD] = (float(*)[HD])(sm + 2 * HD * SP);         // BK x HD
    float (*Ps)[SP] = (float(*)[SP])(sm + 2 * HD * SP + BK * HD); // BQ x SP

    const int qt = blockIdx.x;
    const int h  = blockIdx.y;
    const int b  = blockIdx.z;
    const int tid = threadIdx.x;
    const int ty = tid >> 4;   // rows ty*4..+4
    const int tx = tid & 15;   // cols ty*4..+4 (j for S, d for O)

    const float* Qg = g_q + ((size_t)(b * NH + h) * SEQ + qt * BQ) * HD;
    const float* Kg = g_k + (size_t)(b * NH + h) * SEQ * HD;
    const float* Vg = g_v + (size_t)(b * NH + h) * SEQ * HD;

    // Load Q tile transposed, pre-scaled by 1/sqrt(D)=0.125
    for (int f = tid; f < BQ * (HD / 4); f += 256) {
        int r  = f >> 4;           // 0..63
        int dc = (f & 15) << 2;    // 0..60
        float4 q4 = *(const float4*)(Qg + r * HD + dc);
        Qs[dc + 0][r] = q4.x * 0.125f;
        Qs[dc + 1][r] = q4.y * 0.125f;
        Qs[dc + 2][r] = q4.z * 0.125f;
        Qs[dc + 3][r] = q4.w * 0.125f;
    }

    float m_r[4], l_r[4], acc[4][4];
    #pragma unroll
    for (int i = 0; i < 4; i++) {
        m_r[i] = -1e30f; l_r[i] = 0.f;
        #pragma unroll
        for (int j = 0; j < 4; j++) acc[i][j] = 0.f;
    }

    const int nkt = qt + 1;   // causal: only tiles up to the diagonal
    for (int kt = 0; kt < nkt; kt++) {
        __syncthreads();   // previous P@V done reading Vs/Ps; Q load done (iter 0)
        // Load K (transposed) and V tiles
        for (int f = tid; f < BK * (HD / 4); f += 256) {
            int j  = f >> 4;
            int dc = (f & 15) << 2;
            float4 k4 = *(const float4*)(Kg + (size_t)(kt * BK + j) * HD + dc);
            Ks[dc + 0][j] = k4.x;
            Ks[dc + 1][j] = k4.y;
            Ks[dc + 2][j] = k4.z;
            Ks[dc + 3][j] = k4.w;
            *(float4*)(&Vs[j][dc]) = *(const float4*)(Vg + (size_t)(kt * BK + j) * HD + dc);
        }
        __syncthreads();

        // S[4][4] = (Q K^T) microtile
        float s[4][4];
        #pragma unroll
        for (int i = 0; i < 4; i++)
            #pragma unroll
            for (int j = 0; j < 4; j++) s[i][j] = 0.f;

        #pragma unroll 16
        for (int d = 0; d < HD; d++) {
            float rq[4], rk[4];
            *(float4*)rq = *(float4*)(&Qs[d][ty * 4]);
            *(float4*)rk = *(float4*)(&Ks[d][tx * 4]);
            #pragma unroll
            for (int i = 0; i < 4; i++)
                #pragma unroll
                for (int j = 0; j < 4; j++)
                    s[i][j] += rq[i] * rk[j];
        }

        // Causal mask on the diagonal tile (same tile offset => mask j>i)
        if (kt == qt) {
            #pragma unroll
            for (int i = 0; i < 4; i++) {
                int gi = ty * 4 + i;
                #pragma unroll
                for (int j = 0; j < 4; j++) {
                    int gj = tx * 4 + j;
                    if (gj > gi) s[i][j] = -1e30f;
                }
            }
        }

        // Online softmax update (per row; reduce across the 16 tx lanes)
        #pragma unroll
        for (int i = 0; i < 4; i++) {
            float mx = fmaxf(fmaxf(s[i][0], s[i][1]), fmaxf(s[i][2], s[i][3]));
            #pragma unroll
            for (int o = 8; o >= 1; o >>= 1)
                mx = fmaxf(mx, __shfl_xor_sync(0xffffffff, mx, o));
            float mnew = fmaxf(m_r[i], mx);
            float corr = __expf(m_r[i] - mnew);
            m_r[i] = mnew;

            float rsum = 0.f;
            #pragma unroll
            for (int j = 0; j < 4; j++) {
                float p = __expf(s[i][j] - mnew);
                s[i][j] = p;
                rsum += p;
            }
            #pragma unroll
            for (int o = 8; o >= 1; o >>= 1)
                rsum += __shfl_xor_sync(0xffffffff, rsum, o);
            l_r[i] = l_r[i] * corr + rsum;
            #pragma unroll
            for (int j = 0; j < 4; j++) acc[i][j] *= corr;

            *(float4*)(&Ps[ty * 4 + i][tx * 4]) = *(float4*)(s[i]);
        }
        __syncthreads();   // all P visible before P@V

        // acc += P @ V  (rows ty*4.., d-cols tx*4..)
        #pragma unroll 8
        for (int j = 0; j < BK; j++) {
            float rv[4];
            *(float4*)rv = *(float4*)(&Vs[j][tx * 4]);
            #pragma unroll
            for (int i = 0; i < 4; i++) {
                float p = Ps[ty * 4 + i][j];
                #pragma unroll
                for (int dd = 0; dd < 4; dd++)
                    acc[i][dd] += p * rv[dd];
            }
        }
    }

    // Write output [B, T, C] with C index = h*HD + d
    #pragma unroll
    for (int i = 0; i < 4; i++) {
        int tq = qt * BQ + ty * 4 + i;
        float inv = 1.f / l_r[i];
        float4 o4;
        o4.x = acc[i][0] * inv;
        o4.y = acc[i][1] * inv;
        o4.z = acc[i][2] * inv;
        o4.w = acc[i][3] * inv;
        *(float4*)(out + ((size_t)(b * SEQ + tq) * EMB) + h * HD + tx * 4) = o4;
    }
}

// ---------------------------------------------------------------------------
extern "C" void kernel_launch(void* const* d_in, const int* in_sizes, int n_in,
                              void* d_out, int out_size) {
    const float* x    = (const float*)d_in[0];
    const float* w    = (const float*)d_in[1];
    const float* bias = (const float*)d_in[2];
    float* out = (float*)d_out;

    dim3 g1(N_TOT / 128, M_TOT / 128);   // (24, 32)
    qkv_gemm<<<g1, 256>>>(x, w, bias);

    const size_t smem = (size_t)(2 * HD * SP + BK * HD + BQ * SP) * sizeof(float); // 68608 B
    cudaFuncSetAttribute(attn_kernel, cudaFuncAttributeMaxDynamicSharedMemorySize,
                         (int)smem);
    dim3 g2(SEQ / BQ, NH, BATCH);        // (32, 16, 2)
    attn_kernel<<<g2, 256, smem>>>(out);
}

// round 3
// speedup vs baseline: 1.4974x; 1.4974x over previous
#include <cuda_runtime.h>
#include <cuda_bf16.h>
#include <cstdint>

#define BATCH 2
#define SEQ   2048
#define EMB   1024
#define NH    16
#define HD    64
#define M_TOT (BATCH*SEQ)   // 4096
#define N_TOT (3*EMB)       // 3072
#define K_TOT EMB           // 1024

#define BQ 64
#define BK 64
#define SP 68

// ---------------------------------------------------------------------------
// Device scratch (allocation-free)
// ---------------------------------------------------------------------------
__device__ float g_q[(size_t)BATCH*NH*SEQ*HD];
__device__ float g_k[(size_t)BATCH*NH*SEQ*HD];
__device__ float g_v[(size_t)BATCH*NH*SEQ*HD];

__device__ __nv_bfloat16 g_xh[(size_t)M_TOT*K_TOT];
__device__ __nv_bfloat16 g_xl[(size_t)M_TOT*K_TOT];
__device__ __nv_bfloat16 g_wth[(size_t)N_TOT*K_TOT];   // W^T hi: [N,K]
__device__ __nv_bfloat16 g_wtl[(size_t)N_TOT*K_TOT];   // W^T lo: [N,K]

// ---------------------------------------------------------------------------
// Helpers (arch-portable PTX only: cp.async, ldmatrix, mma.sync)
// ---------------------------------------------------------------------------
__device__ __forceinline__ uint32_t smem_u32(const void* p) {
    uint32_t a;
    asm("{ .reg .u64 t; cvta.to.shared.u64 t, %1; cvt.u32.u64 %0, t; }" : "=r"(a) : "l"(p));
    return a;
}

__device__ __forceinline__ void cp_async16(uint32_t s, const void* g) {
    asm volatile("cp.async.cg.shared.global [%0], [%1], 16;" :: "r"(s), "l"(g) : "memory");
}
#define CP_COMMIT() asm volatile("cp.async.commit_group;" ::: "memory")
#define CP_WAIT(n)  asm volatile("cp.async.wait_group %0;" :: "n"(n) : "memory")

__device__ __forceinline__ void ldsm_x4(uint32_t& r0, uint32_t& r1, uint32_t& r2,
                                        uint32_t& r3, uint32_t addr) {
    asm volatile("ldmatrix.sync.aligned.m8n8.x4.shared.b16 {%0,%1,%2,%3}, [%4];"
                 : "=r"(r0), "=r"(r1), "=r"(r2), "=r"(r3) : "r"(addr));
}

__device__ __forceinline__ void mma_16816(float& c0, float& c1, float& c2, float& c3,
                                          uint32_t a0, uint32_t a1, uint32_t a2, uint32_t a3,
                                          uint32_t b0, uint32_t b1) {
    asm volatile(
        "mma.sync.aligned.m16n8k16.row.col.f32.bf16.bf16.f32 "
        "{%0,%1,%2,%3}, {%4,%5,%6,%7}, {%8,%9}, {%0,%1,%2,%3};"
        : "+f"(c0), "+f"(c1), "+f"(c2), "+f"(c3)
        : "r"(a0), "r"(a1), "r"(a2), "r"(a3), "r"(b0), "r"(b1));
}

// ---------------------------------------------------------------------------
// Split kernels: fp32 -> bf16 hi/lo  (W also transposed to [N,K])
// ---------------------------------------------------------------------------
__global__ void split_x(const float* __restrict__ x) {
    int i = blockIdx.x * 256 + threadIdx.x;      // float4 index, 1M total
    float4 v = ((const float4*)x)[i];
    __nv_bfloat16 h0 = __float2bfloat16(v.x);
    __nv_bfloat16 h1 = __float2bfloat16(v.y);
    __nv_bfloat16 h2 = __float2bfloat16(v.z);
    __nv_bfloat16 h3 = __float2bfloat16(v.w);
    __nv_bfloat16 l0 = __float2bfloat16(v.x - __bfloat162float(h0));
    __nv_bfloat16 l1 = __float2bfloat16(v.y - __bfloat162float(h1));
    __nv_bfloat16 l2 = __float2bfloat16(v.z - __bfloat162float(h2));
    __nv_bfloat16 l3 = __float2bfloat16(v.w - __bfloat162float(h3));
    ((__nv_bfloat162*)g_xh)[2 * i]     = __halves2bfloat162(h0, h1);
    ((__nv_bfloat162*)g_xh)[2 * i + 1] = __halves2bfloat162(h2, h3);
    ((__nv_bfloat162*)g_xl)[2 * i]     = __halves2bfloat162(l0, l1);
    ((__nv_bfloat162*)g_xl)[2 * i + 1] = __halves2bfloat162(l2, l3);
}

__global__ void split_w(const float* __restrict__ w) {
    __shared__ float t[32][33];
    int nb = blockIdx.x * 32, kb = blockIdx.y * 32;
    int tx = threadIdx.x, ty = threadIdx.y;      // (32, 8)
    #pragma unroll
    for (int r = ty; r < 32; r += 8)
        t[r][tx] = w[(size_t)(kb + r) * N_TOT + nb + tx];
    __syncthreads();
    #pragma unroll
    for (int r = ty; r < 32; r += 8) {
        float v = t[tx][r];                      // = w[kb+tx][nb+r]
        __nv_bfloat16 h = __float2bfloat16(v);
        size_t idx = (size_t)(nb + r) * K_TOT + kb + tx;
        g_wth[idx] = h;
        g_wtl[idx] = __float2bfloat16(v - __bfloat162float(h));
    }
}

// ---------------------------------------------------------------------------
// HMMA QKV GEMM: D[128,128] fp32 = (Xh+Xl)(Wh+Wl)^T via 3 bf16 MMA products.
// 8 warps, each 64x32. k-tile 32, cp.async double buffer, ldmatrix fragments.
// smem tile layout: rows padded to 40 bf16 (80B) -> conflict-free ldmatrix.
// ---------------------------------------------------------------------------
#define KT 32
#define PADK 40
#define TILE_B (128 * PADK * 2)       // 10240 bytes per operand tile
#define OFF_AH 0
#define OFF_AL (TILE_B)
#define OFF_BH (2 * TILE_B)
#define OFF_BL (3 * TILE_B)
#define BUF_B  (4 * TILE_B)           // 40960 bytes per buffer

__global__ __launch_bounds__(256, 1) void qkv_tc(const float* __restrict__ bias) {
    extern __shared__ __align__(1024) char smem[];
    const uint32_t sbase = smem_u32(smem);
    const int tid  = threadIdx.x;
    const int lane = tid & 31;
    const int wid  = tid >> 5;
    const int wm   = wid >> 2;        // 0..1 (m 64-blocks)
    const int wn   = wid & 3;         // 0..3 (n 32-blocks)
    const int bnB  = blockIdx.x;      // 0..23
    const int bmB  = blockIdx.y;      // 0..31

    const __nv_bfloat16* Axh = g_xh  + (size_t)(bmB * 128) * K_TOT;
    const __nv_bfloat16* Axl = g_xl  + (size_t)(bmB * 128) * K_TOT;
    const __nv_bfloat16* Bwh = g_wth + (size_t)(bnB * 128) * K_TOT;
    const __nv_bfloat16* Bwl = g_wtl + (size_t)(bnB * 128) * K_TOT;

    // per-thread load slots: f = it*256+tid, row = f>>2, col16 = f&3
    const int r0 = (0 * 256 + tid) >> 2, c0 = (0 * 256 + tid) & 3;
    const int r1 = (1 * 256 + tid) >> 2, c1 = (1 * 256 + tid) & 3;

    auto load_tiles = [&](int ch, int buf) {
        uint32_t sb = sbase + buf * BUF_B;
        const size_t g0 = (size_t)r0 * K_TOT + ch * KT + c0 * 8;
        const size_t g1 = (size_t)r1 * K_TOT + ch * KT + c1 * 8;
        const uint32_t s0 = r0 * (PADK * 2) + c0 * 16;
        const uint32_t s1 = r1 * (PADK * 2) + c1 * 16;
        cp_async16(sb + OFF_AH + s0, Axh + g0);
        cp_async16(sb + OFF_AH + s1, Axh + g1);
        cp_async16(sb + OFF_AL + s0, Axl + g0);
        cp_async16(sb + OFF_AL + s1, Axl + g1);
        cp_async16(sb + OFF_BH + s0, Bwh + g0);
        cp_async16(sb + OFF_BH + s1, Bwh + g1);
        cp_async16(sb + OFF_BL + s0, Bwl + g0);
        cp_async16(sb + OFF_BL + s1, Bwl + g1);
        CP_COMMIT();
    };

    float acc[4][4][4];   // [am][bn][4]
    #pragma unroll
    for (int i = 0; i < 4; i++)
        #pragma unroll
        for (int j = 0; j < 4; j++)
            #pragma unroll
            for (int c = 0; c < 4; c++) acc[i][j][c] = 0.f;

    // ldmatrix lane addressing (bytes)
    // A: row = wm*64 + am*16 + (lane&15), col bf16 = kh*16 + (lane>>4)*8
    const uint32_t a_lane_off = (uint32_t)((wm * 64 + (lane & 15)) * (PADK * 2) + (lane >> 4) * 16);
    // B: row = wn*32 + bp*16 + ((lane>>4)<<3) + (lane&7), col bf16 = kh*16 + ((lane>>3)&1)*8
    const uint32_t b_lane_off = (uint32_t)((wn * 32 + ((lane >> 4) << 3) + (lane & 7)) * (PADK * 2)
                                           + ((lane >> 3) & 1) * 16);

    load_tiles(0, 0);

    const int NCH = K_TOT / KT;   // 32
    for (int ch = 0; ch < NCH; ch++) {
        const int buf = ch & 1;
        if (ch + 1 < NCH) load_tiles(ch + 1, buf ^ 1);
        CP_WAIT(1);
        __syncthreads();

        const uint32_t sb = sbase + buf * BUF_B;
        #pragma unroll
        for (int kh = 0; kh < 2; kh++) {
            const uint32_t kcol = kh * 32;   // kh*16 bf16 = 32 bytes
            uint32_t ah[4][4], al[4][4];
            #pragma unroll
            for (int am = 0; am < 4; am++) {
                uint32_t addr = sb + a_lane_off + am * 16 * (PADK * 2) + kcol;
                ldsm_x4(ah[am][0], ah[am][1], ah[am][2], ah[am][3], addr + OFF_AH);
                ldsm_x4(al[am][0], al[am][1], al[am][2], al[am][3], addr + OFF_AL);
            }
            uint32_t bh[4][2], bl[4][2];
            #pragma unroll
            for (int bp = 0; bp < 2; bp++) {
                uint32_t addr = sb + b_lane_off + bp * 16 * (PADK * 2) + kcol;
                ldsm_x4(bh[bp * 2][0], bh[bp * 2][1], bh[bp * 2 + 1][0], bh[bp * 2 + 1][1],
                        addr + OFF_BH);
                ldsm_x4(bl[bp * 2][0], bl[bp * 2][1], bl[bp * 2 + 1][0], bl[bp * 2 + 1][1],
                        addr + OFF_BL);
            }
            #pragma unroll
            for (int am = 0; am < 4; am++)
                #pragma unroll
                for (int bn = 0; bn < 4; bn++) {
                    mma_16816(acc[am][bn][0], acc[am][bn][1], acc[am][bn][2], acc[am][bn][3],
                              ah[am][0], ah[am][1], ah[am][2], ah[am][3],
                              bh[bn][0], bh[bn][1]);
                    mma_16816(acc[am][bn][0], acc[am][bn][1], acc[am][bn][2], acc[am][bn][3],
                              ah[am][0], ah[am][1], ah[am][2], ah[am][3],
                              bl[bn][0], bl[bn][1]);
                    mma_16816(acc[am][bn][0], acc[am][bn][1], acc[am][bn][2], acc[am][bn][3],
                              al[am][0], al[am][1], al[am][2], al[am][3],
                              bh[bn][0], bh[bn][1]);
                }
        }
        __syncthreads();
    }

    // Epilogue: bias + scatter to [B,H,T,D] (float2 per fragment row-pair)
    const int mq = lane >> 2;         // quad row
    const int nq = (lane & 3) * 2;    // col pair base
    #pragma unroll
    for (int am = 0; am < 4; am++) {
        #pragma unroll
        for (int bn = 0; bn < 4; bn++) {
            int n = bnB * 128 + wn * 32 + bn * 8 + nq;
            float2 bb = *(const float2*)(bias + n);
            int p = n >> 10, cc = n & 1023;
            int h = cc >> 6, d = cc & 63;
            float* dst = (p == 0) ? g_q : (p == 1) ? g_k : g_v;
            #pragma unroll
            for (int half = 0; half < 2; half++) {
                int m = bmB * 128 + wm * 64 + am * 16 + mq + half * 8;
                int b = m >> 11, t = m & 2047;
                float2 v;
                v.x = acc[am][bn][half * 2]     + bb.x;
                v.y = acc[am][bn][half * 2 + 1] + bb.y;
                *(float2*)(dst + ((size_t)(b * NH + h) * SEQ + t) * HD + d) = v;
            }
        }
    }
}

// ---------------------------------------------------------------------------
// Flash attention (fp32, causal) — PV loop blocked 4 j at a time.
// ---------------------------------------------------------------------------
__global__ __launch_bounds__(256) void attn_kernel(float* __restrict__ out) {
    extern __shared__ float sm[];
    float (*Qs)[SP] = (float(*)[SP])(sm);
    float (*Ks)[SP] = (float(*)[SP])(sm + HD * SP);
    float (*Vs)[HD] = (float(*)[HD])(sm + 2 * HD * SP);
    float (*Ps)[SP] = (float(*)[SP])(sm + 2 * HD * SP + BK * HD);

    const int qt = blockIdx.x;
    const int h  = blockIdx.y;
    const int b  = blockIdx.z;
    const int tid = threadIdx.x;
    const int ty = tid >> 4;
    const int tx = tid & 15;

    const float* Qg = g_q + ((size_t)(b * NH + h) * SEQ + qt * BQ) * HD;
    const float* Kg = g_k + (size_t)(b * NH + h) * SEQ * HD;
    const float* Vg = g_v + (size_t)(b * NH + h) * SEQ * HD;

    for (int f = tid; f < BQ * (HD / 4); f += 256) {
        int r = f >> 4, dc = (f & 15) << 2;
        float4 q4 = *(const float4*)(Qg + r * HD + dc);
        Qs[dc + 0][r] = q4.x * 0.125f;
        Qs[dc + 1][r] = q4.y * 0.125f;
        Qs[dc + 2][r] = q4.z * 0.125f;
        Qs[dc + 3][r] = q4.w * 0.125f;
    }

    float m_r[4], l_r[4], acc[4][4];
    #pragma unroll
    for (int i = 0; i < 4; i++) {
        m_r[i] = -1e30f; l_r[i] = 0.f;
        #pragma unroll
        for (int j = 0; j < 4; j++) acc[i][j] = 0.f;
    }

    const int nkt = qt + 1;
    for (int kt = 0; kt < nkt; kt++) {
        __syncthreads();
        for (int f = tid; f < BK * (HD / 4); f += 256) {
            int j = f >> 4, dc = (f & 15) << 2;
            float4 k4 = *(const float4*)(Kg + (size_t)(kt * BK + j) * HD + dc);
            Ks[dc + 0][j] = k4.x;
            Ks[dc + 1][j] = k4.y;
            Ks[dc + 2][j] = k4.z;
            Ks[dc + 3][j] = k4.w;
            *(float4*)(&Vs[j][dc]) = *(const float4*)(Vg + (size_t)(kt * BK + j) * HD + dc);
        }
        __syncthreads();

        float s[4][4];
        #pragma unroll
        for (int i = 0; i < 4; i++)
            #pragma unroll
            for (int j = 0; j < 4; j++) s[i][j] = 0.f;

        #pragma unroll 16
        for (int d = 0; d < HD; d++) {
            float rq[4], rk[4];
            *(float4*)rq = *(float4*)(&Qs[d][ty * 4]);
            *(float4*)rk = *(float4*)(&Ks[d][tx * 4]);
            #pragma unroll
            for (int i = 0; i < 4; i++)
                #pragma unroll
                for (int j = 0; j < 4; j++)
                    s[i][j] += rq[i] * rk[j];
        }

        if (kt == qt) {
            #pragma unroll
            for (int i = 0; i < 4; i++) {
                int gi = ty * 4 + i;
                #pragma unroll
                for (int j = 0; j < 4; j++)
                    if (tx * 4 + j > gi) s[i][j] = -1e30f;
            }
        }

        #pragma unroll
        for (int i = 0; i < 4; i++) {
            float mx = fmaxf(fmaxf(s[i][0], s[i][1]), fmaxf(s[i][2], s[i][3]));
            #pragma unroll
            for (int o = 8; o >= 1; o >>= 1)
                mx = fmaxf(mx, __shfl_xor_sync(0xffffffff, mx, o));
            float mnew = fmaxf(m_r[i], mx);
            float corr = __expf(m_r[i] - mnew);
            m_r[i] = mnew;

            float rsum = 0.f;
            #pragma unroll
            for (int j = 0; j < 4; j++) {
                float p = __expf(s[i][j] - mnew);
                s[i][j] = p;
                rsum += p;
            }
            #pragma unroll
            for (int o = 8; o >= 1; o >>= 1)
                rsum += __shfl_xor_sync(0xffffffff, rsum, o);
            l_r[i] = l_r[i] * corr + rsum;
            #pragma unroll
            for (int j = 0; j < 4; j++) acc[i][j] *= corr;

            *(float4*)(&Ps[ty * 4 + i][tx * 4]) = *(float4*)(s[i]);
        }
        __syncthreads();

        #pragma unroll 4
        for (int j0 = 0; j0 < BK; j0 += 4) {
            float rv[4][4];
            #pragma unroll
            for (int jj = 0; jj < 4; jj++)
                *(float4*)rv[jj] = *(float4*)(&Vs[j0 + jj][tx * 4]);
            #pragma unroll
            for (int i = 0; i < 4; i++) {
                float rp[4];
                *(float4*)rp = *(float4*)(&Ps[ty * 4 + i][j0]);
                #pragma unroll
                for (int jj = 0; jj < 4; jj++)
                    #pragma unroll
                    for (int dd = 0; dd < 4; dd++)
                        acc[i][dd] += rp[jj] * rv[jj][dd];
            }
        }
    }

    #pragma unroll
    for (int i = 0; i < 4; i++) {
        int tq = qt * BQ + ty * 4 + i;
        float inv = 1.f / l_r[i];
        float4 o4;
        o4.x = acc[i][0] * inv;
        o4.y = acc[i][1] * inv;
        o4.z = acc[i][2] * inv;
        o4.w = acc[i][3] * inv;
        *(float4*)(out + ((size_t)(b * SEQ + tq) * EMB) + h * HD + tx * 4) = o4;
    }
}

// ---------------------------------------------------------------------------
extern "C" void kernel_launch(void* const* d_in, const int* in_sizes, int n_in,
                              void* d_out, int out_size) {
    const float* x    = (const float*)d_in[0];
    const float* w    = (const float*)d_in[1];
    const float* bias = (const float*)d_in[2];
    float* out = (float*)d_out;

    split_x<<<M_TOT * K_TOT / (256 * 4), 256>>>(x);
    split_w<<<dim3(N_TOT / 32, K_TOT / 32), dim3(32, 8)>>>(w);

    const int gemm_smem = 2 * BUF_B;   // 81920 B
    cudaFuncSetAttribute(qkv_tc, cudaFuncAttributeMaxDynamicSharedMemorySize, gemm_smem);
    qkv_tc<<<dim3(N_TOT / 128, M_TOT / 128), 256, gemm_smem>>>(bias);

    const size_t smem2 = (size_t)(2 * HD * SP + BK * HD + BQ * SP) * sizeof(float);
    cudaFuncSetAttribute(attn_kernel, cudaFuncAttributeMaxDynamicSharedMemorySize, (int)smem2);
    attn_kernel<<<dim3(SEQ / BQ, NH, BATCH), 256, smem2>>>(out);
}

// round 4
// speedup vs baseline: 2.9560x; 1.9741x over previous
#include <cuda_runtime.h>
#include <cuda_bf16.h>
#include <cstdint>

#define BATCH 2
#define SEQ   2048
#define EMB   1024
#define NH    16
#define HD    64
#define M_TOT (BATCH*SEQ)   // 4096
#define N_TOT (3*EMB)       // 3072
#define K_TOT EMB           // 1024

// ---------------------------------------------------------------------------
// Device scratch (allocation-free)
// ---------------------------------------------------------------------------
__device__ __nv_bfloat16 g_qh[(size_t)BATCH*NH*SEQ*HD];
__device__ __nv_bfloat16 g_ql[(size_t)BATCH*NH*SEQ*HD];
__device__ __nv_bfloat16 g_kh[(size_t)BATCH*NH*SEQ*HD];
__device__ __nv_bfloat16 g_kl[(size_t)BATCH*NH*SEQ*HD];
__device__ __nv_bfloat16 g_vh[(size_t)BATCH*NH*SEQ*HD];
__device__ __nv_bfloat16 g_vl[(size_t)BATCH*NH*SEQ*HD];

__device__ __nv_bfloat16 g_xh[(size_t)M_TOT*K_TOT];
__device__ __nv_bfloat16 g_xl[(size_t)M_TOT*K_TOT];
__device__ __nv_bfloat16 g_wth[(size_t)N_TOT*K_TOT];   // W^T hi: [N,K]
__device__ __nv_bfloat16 g_wtl[(size_t)N_TOT*K_TOT];   // W^T lo: [N,K]

// ---------------------------------------------------------------------------
// Helpers (arch-portable PTX only: cp.async, ldmatrix, mma.sync)
// ---------------------------------------------------------------------------
__device__ __forceinline__ uint32_t smem_u32(const void* p) {
    uint32_t a;
    asm("{ .reg .u64 t; cvta.to.shared.u64 t, %1; cvt.u32.u64 %0, t; }" : "=r"(a) : "l"(p));
    return a;
}

__device__ __forceinline__ void cp_async16(uint32_t s, const void* g) {
    asm volatile("cp.async.cg.shared.global [%0], [%1], 16;" :: "r"(s), "l"(g) : "memory");
}
#define CP_COMMIT() asm volatile("cp.async.commit_group;" ::: "memory")
#define CP_WAIT(n)  asm volatile("cp.async.wait_group %0;" :: "n"(n) : "memory")

__device__ __forceinline__ void ldsm_x4(uint32_t& r0, uint32_t& r1, uint32_t& r2,
                                        uint32_t& r3, uint32_t addr) {
    asm volatile("ldmatrix.sync.aligned.m8n8.x4.shared.b16 {%0,%1,%2,%3}, [%4];"
                 : "=r"(r0), "=r"(r1), "=r"(r2), "=r"(r3) : "r"(addr));
}

__device__ __forceinline__ void ldsm_x4_t(uint32_t& r0, uint32_t& r1, uint32_t& r2,
                                          uint32_t& r3, uint32_t addr) {
    asm volatile("ldmatrix.sync.aligned.m8n8.x4.trans.shared.b16 {%0,%1,%2,%3}, [%4];"
                 : "=r"(r0), "=r"(r1), "=r"(r2), "=r"(r3) : "r"(addr));
}

__device__ __forceinline__ void mma_16816(float& c0, float& c1, float& c2, float& c3,
                                          uint32_t a0, uint32_t a1, uint32_t a2, uint32_t a3,
                                          uint32_t b0, uint32_t b1) {
    asm volatile(
        "mma.sync.aligned.m16n8k16.row.col.f32.bf16.bf16.f32 "
        "{%0,%1,%2,%3}, {%4,%5,%6,%7}, {%8,%9}, {%0,%1,%2,%3};"
        : "+f"(c0), "+f"(c1), "+f"(c2), "+f"(c3)
        : "r"(a0), "r"(a1), "r"(a2), "r"(a3), "r"(b0), "r"(b1));
}
#define MMA4(S, A, B0, B1) \
    mma_16816((S)[0], (S)[1], (S)[2], (S)[3], (A)[0], (A)[1], (A)[2], (A)[3], (B0), (B1))

__device__ __forceinline__ void split2(float x, float y, uint32_t& hi, uint32_t& lo) {
    __nv_bfloat162 h2 = __floats2bfloat162_rn(x, y);
    __nv_bfloat162 l2 = __floats2bfloat162_rn(x - __bfloat162float(h2.x),
                                              y - __bfloat162float(h2.y));
    hi = *reinterpret_cast<uint32_t*>(&h2);
    lo = *reinterpret_cast<uint32_t*>(&l2);
}

// ---------------------------------------------------------------------------
// Split kernels: fp32 -> bf16 hi/lo  (W also transposed to [N,K])
// ---------------------------------------------------------------------------
__global__ void split_x(const float* __restrict__ x) {
    int i = blockIdx.x * 256 + threadIdx.x;
    float4 v = ((const float4*)x)[i];
    __nv_bfloat16 h0 = __float2bfloat16(v.x);
    __nv_bfloat16 h1 = __float2bfloat16(v.y);
    __nv_bfloat16 h2 = __float2bfloat16(v.z);
    __nv_bfloat16 h3 = __float2bfloat16(v.w);
    __nv_bfloat16 l0 = __float2bfloat16(v.x - __bfloat162float(h0));
    __nv_bfloat16 l1 = __float2bfloat16(v.y - __bfloat162float(h1));
    __nv_bfloat16 l2 = __float2bfloat16(v.z - __bfloat162float(h2));
    __nv_bfloat16 l3 = __float2bfloat16(v.w - __bfloat162float(h3));
    ((__nv_bfloat162*)g_xh)[2 * i]     = __halves2bfloat162(h0, h1);
    ((__nv_bfloat162*)g_xh)[2 * i + 1] = __halves2bfloat162(h2, h3);
    ((__nv_bfloat162*)g_xl)[2 * i]     = __halves2bfloat162(l0, l1);
    ((__nv_bfloat162*)g_xl)[2 * i + 1] = __halves2bfloat162(l2, l3);
}

__global__ void split_w(const float* __restrict__ w) {
    __shared__ float t[32][33];
    int nb = blockIdx.x * 32, kb = blockIdx.y * 32;
    int tx = threadIdx.x, ty = threadIdx.y;      // (32, 8)
    #pragma unroll
    for (int r = ty; r < 32; r += 8)
        t[r][tx] = w[(size_t)(kb + r) * N_TOT + nb + tx];
    __syncthreads();
    #pragma unroll
    for (int r = ty; r < 32; r += 8) {
        float v = t[tx][r];
        __nv_bfloat16 h = __float2bfloat16(v);
        size_t idx = (size_t)(nb + r) * K_TOT + kb + tx;
        g_wth[idx] = h;
        g_wtl[idx] = __float2bfloat16(v - __bfloat162float(h));
    }
}

// ---------------------------------------------------------------------------
// HMMA QKV GEMM (as round 3), epilogue now emits bf16 hi/lo Q/K/V in [B,H,T,D]
// (Q pre-scaled by 1/sqrt(HD) = 0.125).
// ---------------------------------------------------------------------------
#define KT 32
#define PADK 40
#define TILE_B (128 * PADK * 2)
#define OFF_AH 0
#define OFF_AL (TILE_B)
#define OFF_BH (2 * TILE_B)
#define OFF_BL (3 * TILE_B)
#define BUF_B  (4 * TILE_B)

__global__ __launch_bounds__(256, 1) void qkv_tc(const float* __restrict__ bias) {
    extern __shared__ __align__(1024) char smem[];
    const uint32_t sbase = smem_u32(smem);
    const int tid  = threadIdx.x;
    const int lane = tid & 31;
    const int wid  = tid >> 5;
    const int wm   = wid >> 2;
    const int wn   = wid & 3;
    const int bnB  = blockIdx.x;
    const int bmB  = blockIdx.y;

    const __nv_bfloat16* Axh = g_xh  + (size_t)(bmB * 128) * K_TOT;
    const __nv_bfloat16* Axl = g_xl  + (size_t)(bmB * 128) * K_TOT;
    const __nv_bfloat16* Bwh = g_wth + (size_t)(bnB * 128) * K_TOT;
    const __nv_bfloat16* Bwl = g_wtl + (size_t)(bnB * 128) * K_TOT;

    const int r0 = (0 * 256 + tid) >> 2, c0 = (0 * 256 + tid) & 3;
    const int r1 = (1 * 256 + tid) >> 2, c1 = (1 * 256 + tid) & 3;

    auto load_tiles = [&](int ch, int buf) {
        uint32_t sb = sbase + buf * BUF_B;
        const size_t g0 = (size_t)r0 * K_TOT + ch * KT + c0 * 8;
        const size_t g1 = (size_t)r1 * K_TOT + ch * KT + c1 * 8;
        const uint32_t s0 = r0 * (PADK * 2) + c0 * 16;
        const uint32_t s1 = r1 * (PADK * 2) + c1 * 16;
        cp_async16(sb + OFF_AH + s0, Axh + g0);
        cp_async16(sb + OFF_AH + s1, Axh + g1);
        cp_async16(sb + OFF_AL + s0, Axl + g0);
        cp_async16(sb + OFF_AL + s1, Axl + g1);
        cp_async16(sb + OFF_BH + s0, Bwh + g0);
        cp_async16(sb + OFF_BH + s1, Bwh + g1);
        cp_async16(sb + OFF_BL + s0, Bwl + g0);
        cp_async16(sb + OFF_BL + s1, Bwl + g1);
        CP_COMMIT();
    };

    float acc[4][4][4];
    #pragma unroll
    for (int i = 0; i < 4; i++)
        #pragma unroll
        for (int j = 0; j < 4; j++)
            #pragma unroll
            for (int c = 0; c < 4; c++) acc[i][j][c] = 0.f;

    const uint32_t a_lane_off = (uint32_t)((wm * 64 + (lane & 15)) * (PADK * 2) + (lane >> 4) * 16);
    const uint32_t b_lane_off = (uint32_t)((wn * 32 + ((lane >> 4) << 3) + (lane & 7)) * (PADK * 2)
                                           + ((lane >> 3) & 1) * 16);

    load_tiles(0, 0);

    const int NCH = K_TOT / KT;
    for (int ch = 0; ch < NCH; ch++) {
        const int buf = ch & 1;
        if (ch + 1 < NCH) load_tiles(ch + 1, buf ^ 1);
        CP_WAIT(1);
        __syncthreads();

        const uint32_t sb = sbase + buf * BUF_B;
        #pragma unroll
        for (int kh = 0; kh < 2; kh++) {
            const uint32_t kcol = kh * 32;
            uint32_t ah[4][4], al[4][4];
            #pragma unroll
            for (int am = 0; am < 4; am++) {
                uint32_t addr = sb + a_lane_off + am * 16 * (PADK * 2) + kcol;
                ldsm_x4(ah[am][0], ah[am][1], ah[am][2], ah[am][3], addr + OFF_AH);
                ldsm_x4(al[am][0], al[am][1], al[am][2], al[am][3], addr + OFF_AL);
            }
            uint32_t bh[4][2], bl[4][2];
            #pragma unroll
            for (int bp = 0; bp < 2; bp++) {
                uint32_t addr = sb + b_lane_off + bp * 16 * (PADK * 2) + kcol;
                ldsm_x4(bh[bp * 2][0], bh[bp * 2][1], bh[bp * 2 + 1][0], bh[bp * 2 + 1][1],
                        addr + OFF_BH);
                ldsm_x4(bl[bp * 2][0], bl[bp * 2][1], bl[bp * 2 + 1][0], bl[bp * 2 + 1][1],
                        addr + OFF_BL);
            }
            #pragma unroll
            for (int am = 0; am < 4; am++)
                #pragma unroll
                for (int bn = 0; bn < 4; bn++) {
                    MMA4(acc[am][bn], ah[am], bh[bn][0], bh[bn][1]);
                    MMA4(acc[am][bn], ah[am], bl[bn][0], bl[bn][1]);
                    MMA4(acc[am][bn], al[am], bh[bn][0], bh[bn][1]);
                }
        }
        __syncthreads();
    }

    // Epilogue: bias, scale Q, split to bf16 hi/lo, scatter to [B,H,T,D]
    const int mq = lane >> 2;
    const int nq = (lane & 3) * 2;
    #pragma unroll
    for (int am = 0; am < 4; am++) {
        #pragma unroll
        for (int bn = 0; bn < 4; bn++) {
            int n = bnB * 128 + wn * 32 + bn * 8 + nq;
            float2 bb = *(const float2*)(bias + n);
            int p = n >> 10, cc = n & 1023;
            int hh = cc >> 6, d = cc & 63;
            __nv_bfloat16 *dh, *dl;
            if (p == 0)      { dh = g_qh; dl = g_ql; }
            else if (p == 1) { dh = g_kh; dl = g_kl; }
            else             { dh = g_vh; dl = g_vl; }
            float sc = (p == 0) ? 0.125f : 1.0f;
            #pragma unroll
            for (int half = 0; half < 2; half++) {
                int m = bmB * 128 + wm * 64 + am * 16 + mq + half * 8;
                int bi = m >> 11, t = m & 2047;
                float vx = (acc[am][bn][half * 2]     + bb.x) * sc;
                float vy = (acc[am][bn][half * 2 + 1] + bb.y) * sc;
                uint32_t hi, lo;
                split2(vx, vy, hi, lo);
                size_t idx = ((size_t)(bi * NH + hh) * SEQ + t) * HD + d;
                *(uint32_t*)(dh + idx) = hi;
                *(uint32_t*)(dl + idx) = lo;
            }
        }
    }
}

// ---------------------------------------------------------------------------
// Tensor-core flash attention (causal), bf16 hi/lo split everywhere.
// CTA: 64 Q rows, 4 warps (16 rows each), BK=64, double-buffered K/V.
// ---------------------------------------------------------------------------
#define AST  72                 // smem row stride (bf16)
#define ASTB 144                // bytes
#define TILE9 (64 * ASTB)       // 9216 B per 64x64 tile
#define QH_OFF 0
#define QL_OFF TILE9
#define KV_OFF (2 * TILE9)
#define KVBUF  (4 * TILE9)      // Kh,Kl,Vh,Vl

__global__ __launch_bounds__(128, 2) void attn_mma(float* __restrict__ out) {
    extern __shared__ __align__(1024) char smem[];
    const uint32_t sb = smem_u32(smem);
    const int tid = threadIdx.x, lane = tid & 31, wid = tid >> 5;
    const int qt = blockIdx.x, hh = blockIdx.y, bb = blockIdx.z;

    const size_t head = (size_t)(bb * NH + hh) * SEQ * HD;
    const char* Qhg = (const char*)(g_qh + head + (size_t)qt * 64 * HD);
    const char* Qlg = (const char*)(g_ql + head + (size_t)qt * 64 * HD);
    const char* Khg = (const char*)(g_kh + head);
    const char* Klg = (const char*)(g_kl + head);
    const char* Vhg = (const char*)(g_vh + head);
    const char* Vlg = (const char*)(g_vl + head);

    // Q -> smem (64 rows x 128B each)
    #pragma unroll
    for (int i = 0; i < 4; i++) {
        int f = i * 128 + tid;
        int r = f >> 3, c = (f & 7) * 16;
        cp_async16(sb + QH_OFF + r * ASTB + c, Qhg + r * 128 + c);
        cp_async16(sb + QL_OFF + r * ASTB + c, Qlg + r * 128 + c);
    }
    CP_COMMIT();

    auto load_kv = [&](int kt, int buf) {
        uint32_t base = sb + KV_OFF + buf * KVBUF;
        size_t go0 = (size_t)kt * 64 * 128;
        #pragma unroll
        for (int i = 0; i < 4; i++) {
            int f = i * 128 + tid;
            int r = f >> 3, c = (f & 7) * 16;
            uint32_t so = r * ASTB + c;
            size_t go = go0 + r * 128 + c;
            cp_async16(base + so,             Khg + go);
            cp_async16(base + TILE9 + so,     Klg + go);
            cp_async16(base + 2 * TILE9 + so, Vhg + go);
            cp_async16(base + 3 * TILE9 + so, Vlg + go);
        }
        CP_COMMIT();
    };

    load_kv(0, 0);
    CP_WAIT(1);                 // Q group done
    __syncthreads();

    // Q fragments, resident all kernel
    uint32_t qh[4][4], ql[4][4];
    const uint32_t a_off = (uint32_t)((wid * 16 + (lane & 15)) * ASTB + (lane >> 4) * 16);
    #pragma unroll
    for (int ks = 0; ks < 4; ks++) {
        ldsm_x4(qh[ks][0], qh[ks][1], qh[ks][2], qh[ks][3], sb + QH_OFF + a_off + ks * 32);
        ldsm_x4(ql[ks][0], ql[ks][1], ql[ks][2], ql[ks][3], sb + QL_OFF + a_off + ks * 32);
    }

    float o[8][4];
    #pragma unroll
    for (int nt = 0; nt < 8; nt++)
        #pragma unroll
        for (int c = 0; c < 4; c++) o[nt][c] = 0.f;
    float m0 = -1e30f, m1 = -1e30f, l0 = 0.f, l1 = 0.f;

    const uint32_t kb_off = (uint32_t)(((((lane >> 4) << 3) + (lane & 7))) * ASTB
                                       + ((lane >> 3) & 1) * 16);
    const uint32_t vt_off = (uint32_t)(((((lane >> 3) & 1) * 8 + (lane & 7))) * ASTB
                                       + (lane >> 4) * 16);

    const int nkt = qt + 1;
    for (int kt = 0; kt < nkt; kt++) {
        const int buf = kt & 1;
        if (kt + 1 < nkt) { load_kv(kt + 1, buf ^ 1); CP_WAIT(1); }
        else              { CP_WAIT(0); }
        __syncthreads();

        const uint32_t kvb = sb + KV_OFF + buf * KVBUF;

        // ---- S = Q K^T (3-way split) ----
        float s[8][4];
        #pragma unroll
        for (int nt = 0; nt < 8; nt++)
            #pragma unroll
            for (int c = 0; c < 4; c++) s[nt][c] = 0.f;

        #pragma unroll
        for (int nt16 = 0; nt16 < 4; nt16++) {
            #pragma unroll
            for (int ks = 0; ks < 4; ks++) {
                uint32_t k0, k1, k2, k3, e0, e1, e2, e3;
                uint32_t addr = kvb + kb_off + nt16 * 16 * ASTB + ks * 32;
                ldsm_x4(k0, k1, k2, k3, addr);              // Kh
                ldsm_x4(e0, e1, e2, e3, addr + TILE9);      // Kl
                const int nA = nt16 * 2, nB = nA + 1;
                MMA4(s[nA], qh[ks], k0, k1);
                MMA4(s[nA], qh[ks], e0, e1);
                MMA4(s[nA], ql[ks], k0, k1);
                MMA4(s[nB], qh[ks], k2, k3);
                MMA4(s[nB], qh[ks], e2, e3);
                MMA4(s[nB], ql[ks], k2, k3);
            }
        }

        // ---- causal mask (diagonal tile only) ----
        if (kt == qt) {
            const int qr = wid * 16 + (lane >> 2);
            #pragma unroll
            for (int nt = 0; nt < 8; nt++) {
                int j0 = nt * 8 + (lane & 3) * 2;
                if (j0     > qr)     s[nt][0] = -1e30f;
                if (j0 + 1 > qr)     s[nt][1] = -1e30f;
                if (j0     > qr + 8) s[nt][2] = -1e30f;
                if (j0 + 1 > qr + 8) s[nt][3] = -1e30f;
            }
        }

        // ---- online softmax (rows qr, qr+8; quad reduce) ----
        float mx0 = -1e30f, mx1 = -1e30f;
        #pragma unroll
        for (int nt = 0; nt < 8; nt++) {
            mx0 = fmaxf(mx0, fmaxf(s[nt][0], s[nt][1]));
            mx1 = fmaxf(mx1, fmaxf(s[nt][2], s[nt][3]));
        }
        mx0 = fmaxf(mx0, __shfl_xor_sync(0xffffffffu, mx0, 1));
        mx0 = fmaxf(mx0, __shfl_xor_sync(0xffffffffu, mx0, 2));
        mx1 = fmaxf(mx1, __shfl_xor_sync(0xffffffffu, mx1, 1));
        mx1 = fmaxf(mx1, __shfl_xor_sync(0xffffffffu, mx1, 2));
        float mn0 = fmaxf(m0, mx0), mn1 = fmaxf(m1, mx1);
        float cr0 = __expf(m0 - mn0), cr1 = __expf(m1 - mn1);
        m0 = mn0; m1 = mn1;

        float t0 = 0.f, t1 = 0.f;
        #pragma unroll
        for (int nt = 0; nt < 8; nt++) {
            s[nt][0] = __expf(s[nt][0] - mn0); t0 += s[nt][0];
            s[nt][1] = __expf(s[nt][1] - mn0); t0 += s[nt][1];
            s[nt][2] = __expf(s[nt][2] - mn1); t1 += s[nt][2];
            s[nt][3] = __expf(s[nt][3] - mn1); t1 += s[nt][3];
        }
        t0 += __shfl_xor_sync(0xffffffffu, t0, 1);
        t0 += __shfl_xor_sync(0xffffffffu, t0, 2);
        t1 += __shfl_xor_sync(0xffffffffu, t1, 1);
        t1 += __shfl_xor_sync(0xffffffffu, t1, 2);
        l0 = l0 * cr0 + t0;
        l1 = l1 * cr1 + t1;
        #pragma unroll
        for (int nt = 0; nt < 8; nt++) {
            o[nt][0] *= cr0; o[nt][1] *= cr0;
            o[nt][2] *= cr1; o[nt][3] *= cr1;
        }

        // ---- P -> bf16 hi/lo A-fragments ----
        uint32_t ph[4][4], pl[4][4];
        #pragma unroll
        for (int t = 0; t < 4; t++) {
            split2(s[2 * t][0],     s[2 * t][1],     ph[t][0], pl[t][0]);
            split2(s[2 * t][2],     s[2 * t][3],     ph[t][1], pl[t][1]);
            split2(s[2 * t + 1][0], s[2 * t + 1][1], ph[t][2], pl[t][2]);
            split2(s[2 * t + 1][2], s[2 * t + 1][3], ph[t][3], pl[t][3]);
        }

        // ---- O += P V (3-way split), V via ldmatrix.trans ----
        #pragma unroll
        for (int g = 0; g < 4; g++) {
            #pragma unroll
            for (int t = 0; t < 4; t++) {
                uint32_t v0, v1, v2, v3, w0, w1, w2, w3;
                uint32_t addr = kvb + 2 * TILE9 + vt_off + t * 16 * ASTB + g * 32;
                ldsm_x4_t(v0, v1, v2, v3, addr);            // Vh
                ldsm_x4_t(w0, w1, w2, w3, addr + TILE9);    // Vl
                const int nA = g * 2, nB = nA + 1;
                MMA4(o[nA], ph[t], v0, v1);
                MMA4(o[nA], ph[t], w0, w1);
                MMA4(o[nA], pl[t], v0, v1);
                MMA4(o[nB], ph[t], v2, v3);
                MMA4(o[nB], ph[t], w2, w3);
                MMA4(o[nB], pl[t], v2, v3);
            }
        }
        __syncthreads();   // protect K/V buffer before next iteration's cp.async
    }

    // ---- epilogue ----
    float il0 = 1.f / l0, il1 = 1.f / l1;
    int trow = qt * 64 + wid * 16 + (lane >> 2);
    #pragma unroll
    for (int nt = 0; nt < 8; nt++) {
        int d = nt * 8 + (lane & 3) * 2;
        float2 u0 = make_float2(o[nt][0] * il0, o[nt][1] * il0);
        float2 u1 = make_float2(o[nt][2] * il1, o[nt][3] * il1);
        *(float2*)(out + ((size_t)(bb * SEQ + trow)     * EMB) + hh * 64 + d) = u0;
        *(float2*)(out + ((size_t)(bb * SEQ + trow + 8) * EMB) + hh * 64 + d) = u1;
    }
}

// ---------------------------------------------------------------------------
extern "C" void kernel_launch(void* const* d_in, const int* in_sizes, int n_in,
                              void* d_out, int out_size) {
    const float* x    = (const float*)d_in[0];
    const float* w    = (const float*)d_in[1];
    const float* bias = (const float*)d_in[2];
    float* out = (float*)d_out;

    split_x<<<M_TOT * K_TOT / (256 * 4), 256>>>(x);
    split_w<<<dim3(N_TOT / 32, K_TOT / 32), dim3(32, 8)>>>(w);

    const int gemm_smem = 2 * BUF_B;   // 81920 B
    cudaFuncSetAttribute(qkv_tc, cudaFuncAttributeMaxDynamicSharedMemorySize, gemm_smem);
    qkv_tc<<<dim3(N_TOT / 128, M_TOT / 128), 256, gemm_smem>>>(bias);

    const int attn_smem = 2 * TILE9 + 2 * KVBUF;   // 92160 B
    cudaFuncSetAttribute(attn_mma, cudaFuncAttributeMaxDynamicSharedMemorySize, attn_smem);
    attn_mma<<<dim3(SEQ / 64, NH, BATCH), 128, attn_smem>>>(out);
}

// round 5
// speedup vs baseline: 3.1423x; 1.0630x over previous
#include <cuda_runtime.h>
#include <cuda_bf16.h>
#include <cstdint>

#define BATCH 2
#define SEQ   2048
#define EMB   1024
#define NH    16
#define HD    64
#define M_TOT (BATCH*SEQ)   // 4096
#define N_TOT (3*EMB)       // 3072
#define K_TOT EMB           // 1024

// ---------------------------------------------------------------------------
// Device scratch (allocation-free)
// ---------------------------------------------------------------------------
__device__ __nv_bfloat16 g_qh[(size_t)BATCH*NH*SEQ*HD];
__device__ __nv_bfloat16 g_ql[(size_t)BATCH*NH*SEQ*HD];
__device__ __nv_bfloat16 g_kh[(size_t)BATCH*NH*SEQ*HD];
__device__ __nv_bfloat16 g_kl[(size_t)BATCH*NH*SEQ*HD];
__device__ __nv_bfloat16 g_vh[(size_t)BATCH*NH*SEQ*HD];
__device__ __nv_bfloat16 g_vl[(size_t)BATCH*NH*SEQ*HD];

__device__ __nv_bfloat16 g_xh[(size_t)M_TOT*K_TOT];
__device__ __nv_bfloat16 g_xl[(size_t)M_TOT*K_TOT];
__device__ __nv_bfloat16 g_wth[(size_t)N_TOT*K_TOT];   // W^T hi: [N,K]
__device__ __nv_bfloat16 g_wtl[(size_t)N_TOT*K_TOT];   // W^T lo: [N,K]

// ---------------------------------------------------------------------------
// Helpers (arch-portable PTX only: cp.async, ldmatrix, mma.sync)
// ---------------------------------------------------------------------------
__device__ __forceinline__ uint32_t smem_u32(const void* p) {
    uint32_t a;
    asm("{ .reg .u64 t; cvta.to.shared.u64 t, %1; cvt.u32.u64 %0, t; }" : "=r"(a) : "l"(p));
    return a;
}

__device__ __forceinline__ void cp_async16(uint32_t s, const void* g) {
    asm volatile("cp.async.cg.shared.global [%0], [%1], 16;" :: "r"(s), "l"(g) : "memory");
}
#define CP_COMMIT() asm volatile("cp.async.commit_group;" ::: "memory")
#define CP_WAIT(n)  asm volatile("cp.async.wait_group %0;" :: "n"(n) : "memory")

__device__ __forceinline__ void ldsm_x4(uint32_t& r0, uint32_t& r1, uint32_t& r2,
                                        uint32_t& r3, uint32_t addr) {
    asm volatile("ldmatrix.sync.aligned.m8n8.x4.shared.b16 {%0,%1,%2,%3}, [%4];"
                 : "=r"(r0), "=r"(r1), "=r"(r2), "=r"(r3) : "r"(addr));
}

__device__ __forceinline__ void ldsm_x4_t(uint32_t& r0, uint32_t& r1, uint32_t& r2,
                                          uint32_t& r3, uint32_t addr) {
    asm volatile("ldmatrix.sync.aligned.m8n8.x4.trans.shared.b16 {%0,%1,%2,%3}, [%4];"
                 : "=r"(r0), "=r"(r1), "=r"(r2), "=r"(r3) : "r"(addr));
}

__device__ __forceinline__ void mma_16816(float& c0, float& c1, float& c2, float& c3,
                                          uint32_t a0, uint32_t a1, uint32_t a2, uint32_t a3,
                                          uint32_t b0, uint32_t b1) {
    asm volatile(
        "mma.sync.aligned.m16n8k16.row.col.f32.bf16.bf16.f32 "
        "{%0,%1,%2,%3}, {%4,%5,%6,%7}, {%8,%9}, {%0,%1,%2,%3};"
        : "+f"(c0), "+f"(c1), "+f"(c2), "+f"(c3)
        : "r"(a0), "r"(a1), "r"(a2), "r"(a3), "r"(b0), "r"(b1));
}
#define MMA4(S, A, B0, B1) \
    mma_16816((S)[0], (S)[1], (S)[2], (S)[3], (A)[0], (A)[1], (A)[2], (A)[3], (B0), (B1))

__device__ __forceinline__ void split2(float x, float y, uint32_t& hi, uint32_t& lo) {
    __nv_bfloat162 h2 = __floats2bfloat162_rn(x, y);
    __nv_bfloat162 l2 = __floats2bfloat162_rn(x - __bfloat162float(h2.x),
                                              y - __bfloat162float(h2.y));
    hi = *reinterpret_cast<uint32_t*>(&h2);
    lo = *reinterpret_cast<uint32_t*>(&l2);
}

// ---------------------------------------------------------------------------
// Split kernels: fp32 -> bf16 hi/lo  (W also transposed to [N,K])
// ---------------------------------------------------------------------------
__global__ void split_x(const float* __restrict__ x) {
    int i = blockIdx.x * 256 + threadIdx.x;
    float4 v = ((const float4*)x)[i];
    __nv_bfloat16 h0 = __float2bfloat16(v.x);
    __nv_bfloat16 h1 = __float2bfloat16(v.y);
    __nv_bfloat16 h2 = __float2bfloat16(v.z);
    __nv_bfloat16 h3 = __float2bfloat16(v.w);
    __nv_bfloat16 l0 = __float2bfloat16(v.x - __bfloat162float(h0));
    __nv_bfloat16 l1 = __float2bfloat16(v.y - __bfloat162float(h1));
    __nv_bfloat16 l2 = __float2bfloat16(v.z - __bfloat162float(h2));
    __nv_bfloat16 l3 = __float2bfloat16(v.w - __bfloat162float(h3));
    ((__nv_bfloat162*)g_xh)[2 * i]     = __halves2bfloat162(h0, h1);
    ((__nv_bfloat162*)g_xh)[2 * i + 1] = __halves2bfloat162(h2, h3);
    ((__nv_bfloat162*)g_xl)[2 * i]     = __halves2bfloat162(l0, l1);
    ((__nv_bfloat162*)g_xl)[2 * i + 1] = __halves2bfloat162(l2, l3);
}

__global__ void split_w(const float* __restrict__ w) {
    __shared__ float t[32][33];
    int nb = blockIdx.x * 32, kb = blockIdx.y * 32;
    int tx = threadIdx.x, ty = threadIdx.y;      // (32, 8)
    #pragma unroll
    for (int r = ty; r < 32; r += 8)
        t[r][tx] = w[(size_t)(kb + r) * N_TOT + nb + tx];
    __syncthreads();
    #pragma unroll
    for (int r = ty; r < 32; r += 8) {
        float v = t[tx][r];
        __nv_bfloat16 h = __float2bfloat16(v);
        size_t idx = (size_t)(nb + r) * K_TOT + kb + tx;
        g_wth[idx] = h;
        g_wtl[idx] = __float2bfloat16(v - __bfloat162float(h));
    }
}

// ---------------------------------------------------------------------------
// HMMA QKV GEMM, CTA tile 256(M) x 128(N), 8 warps each 64x64, k-tile 32,
// cp.async double buffer. Epilogue emits bf16 hi/lo Q/K/V in [B,H,T,D]
// (Q pre-scaled by 1/sqrt(HD) = 0.125).
// ---------------------------------------------------------------------------
#define KT 32
#define PADK 40
#define ROWB (PADK * 2)               // 80 B row stride
#define ATILE (256 * ROWB)            // 20480 B
#define BTILE (128 * ROWB)            // 10240 B
#define OFF_AH 0
#define OFF_AL (ATILE)
#define OFF_BH (2 * ATILE)
#define OFF_BL (2 * ATILE + BTILE)
#define BUF_B  (2 * ATILE + 2 * BTILE)   // 61440 B

__global__ __launch_bounds__(256, 1) void qkv_tc(const float* __restrict__ bias) {
    extern __shared__ __align__(1024) char smem[];
    const uint32_t sbase = smem_u32(smem);
    const int tid  = threadIdx.x;
    const int lane = tid & 31;
    const int wid  = tid >> 5;
    const int wm   = wid >> 1;        // 0..3 (m 64-blocks)
    const int wn   = wid & 1;         // 0..1 (n 64-blocks)
    const int bnB  = blockIdx.x;      // 0..23
    const int bmB  = blockIdx.y;      // 0..15

    const __nv_bfloat16* Axh = g_xh  + (size_t)(bmB * 256) * K_TOT;
    const __nv_bfloat16* Axl = g_xl  + (size_t)(bmB * 256) * K_TOT;
    const __nv_bfloat16* Bwh = g_wth + (size_t)(bnB * 128) * K_TOT;
    const __nv_bfloat16* Bwl = g_wtl + (size_t)(bnB * 128) * K_TOT;

    auto load_tiles = [&](int ch, int buf) {
        uint32_t sb = sbase + buf * BUF_B;
        #pragma unroll
        for (int it = 0; it < 4; it++) {          // A: 256 rows x 64B
            int f = it * 256 + tid;
            int r = f >> 2, c = f & 3;
            size_t g = (size_t)r * K_TOT + ch * KT + c * 8;
            uint32_t s = r * ROWB + c * 16;
            cp_async16(sb + OFF_AH + s, Axh + g);
            cp_async16(sb + OFF_AL + s, Axl + g);
        }
        #pragma unroll
        for (int it = 0; it < 2; it++) {          // B: 128 rows x 64B
            int f = it * 256 + tid;
            int r = f >> 2, c = f & 3;
            size_t g = (size_t)r * K_TOT + ch * KT + c * 8;
            uint32_t s = r * ROWB + c * 16;
            cp_async16(sb + OFF_BH + s, Bwh + g);
            cp_async16(sb + OFF_BL + s, Bwl + g);
        }
        CP_COMMIT();
    };

    float acc[4][8][4];   // [am 16-row][bn 8-col][frag]
    #pragma unroll
    for (int i = 0; i < 4; i++)
        #pragma unroll
        for (int j = 0; j < 8; j++)
            #pragma unroll
            for (int c = 0; c < 4; c++) acc[i][j][c] = 0.f;

    const uint32_t a_lane_off = (uint32_t)((wm * 64 + (lane & 15)) * ROWB + (lane >> 4) * 16);
    const uint32_t b_lane_off = (uint32_t)((wn * 64 + ((lane >> 4) << 3) + (lane & 7)) * ROWB
                                           + ((lane >> 3) & 1) * 16);

    load_tiles(0, 0);

    const int NCH = K_TOT / KT;   // 32
    for (int ch = 0; ch < NCH; ch++) {
        const int buf = ch & 1;
        if (ch + 1 < NCH) load_tiles(ch + 1, buf ^ 1);
        CP_WAIT(1);
        __syncthreads();

        const uint32_t sb = sbase + buf * BUF_B;
        #pragma unroll
        for (int kh = 0; kh < 2; kh++) {
            const uint32_t kcol = kh * 32;   // kh*16 bf16 = 32 B
            uint32_t ah[4][4], al[4][4];
            #pragma unroll
            for (int am = 0; am < 4; am++) {
                uint32_t addr = sb + a_lane_off + am * 16 * ROWB + kcol;
                ldsm_x4(ah[am][0], ah[am][1], ah[am][2], ah[am][3], addr + OFF_AH);
                ldsm_x4(al[am][0], al[am][1], al[am][2], al[am][3], addr + OFF_AL);
            }
            #pragma unroll
            for (int bp = 0; bp < 4; bp++) {       // stream B 2 bn-tiles at a time
                uint32_t b0, b1, b2, b3, c0, c1, c2, c3;
                uint32_t addr = sb + OFF_BH + b_lane_off + bp * 16 * ROWB + kcol;
                ldsm_x4(b0, b1, b2, b3, addr);             // Bh
                ldsm_x4(c0, c1, c2, c3, addr + BTILE);     // Bl
                const int nA = bp * 2, nB = nA + 1;
                #pragma unroll
                for (int am = 0; am < 4; am++) {
                    MMA4(acc[am][nA], ah[am], b0, b1);
                    MMA4(acc[am][nA], ah[am], c0, c1);
                    MMA4(acc[am][nA], al[am], b0, b1);
                    MMA4(acc[am][nB], ah[am], b2, b3);
                    MMA4(acc[am][nB], ah[am], c2, c3);
                    MMA4(acc[am][nB], al[am], b2, b3);
                }
            }
        }
        __syncthreads();
    }

    // Epilogue: bias, scale Q, split to bf16 hi/lo, scatter to [B,H,T,D]
    const int mq = lane >> 2;
    const int nq = (lane & 3) * 2;
    const int nbase = bnB * 128 + wn * 64;       // 64-aligned: p constant per warp
    const int p = nbase >> 10;
    __nv_bfloat16 *dh, *dl;
    if (p == 0)      { dh = g_qh; dl = g_ql; }
    else if (p == 1) { dh = g_kh; dl = g_kl; }
    else             { dh = g_vh; dl = g_vl; }
    const float sc = (p == 0) ? 0.125f : 1.0f;

    #pragma unroll
    for (int bn = 0; bn < 8; bn++) {
        int n = nbase + bn * 8 + nq;
        float2 bb = *(const float2*)(bias + n);
        int cc = n & 1023;
        int hh = cc >> 6, d = cc & 63;
        #pragma unroll
        for (int am = 0; am < 4; am++) {
            #pragma unroll
            for (int half = 0; half < 2; half++) {
                int m = bmB * 256 + wm * 64 + am * 16 + mq + half * 8;
                int bi = m >> 11, t = m & 2047;
                float vx = (acc[am][bn][half * 2]     + bb.x) * sc;
                float vy = (acc[am][bn][half * 2 + 1] + bb.y) * sc;
                uint32_t hi, lo;
                split2(vx, vy, hi, lo);
                size_t idx = ((size_t)(bi * NH + hh) * SEQ + t) * HD + d;
                *(uint32_t*)(dh + idx) = hi;
                *(uint32_t*)(dl + idx) = lo;
            }
        }
    }
}

// ---------------------------------------------------------------------------
// Tensor-core flash attention (causal), bf16 hi/lo split everywhere.
// CTA: 64 Q rows, 4 warps (16 rows each), BK=64, double-buffered K/V.
// ---------------------------------------------------------------------------
#define AST  72                 // smem row stride (bf16)
#define ASTB 144                // bytes
#define TILE9 (64 * ASTB)       // 9216 B per 64x64 tile
#define QH_OFF 0
#define QL_OFF TILE9
#define KV_OFF (2 * TILE9)
#define KVBUF  (4 * TILE9)      // Kh,Kl,Vh,Vl

__global__ __launch_bounds__(128, 2) void attn_mma(float* __restrict__ out) {
    extern __shared__ __align__(1024) char smem[];
    const uint32_t sb = smem_u32(smem);
    const int tid = threadIdx.x, lane = tid & 31, wid = tid >> 5;
    const int qt = blockIdx.x, hh = blockIdx.y, bb = blockIdx.z;

    const size_t head = (size_t)(bb * NH + hh) * SEQ * HD;
    const char* Qhg = (const char*)(g_qh + head + (size_t)qt * 64 * HD);
    const char* Qlg = (const char*)(g_ql + head + (size_t)qt * 64 * HD);
    const char* Khg = (const char*)(g_kh + head);
    const char* Klg = (const char*)(g_kl + head);
    const char* Vhg = (const char*)(g_vh + head);
    const char* Vlg = (const char*)(g_vl + head);

    #pragma unroll
    for (int i = 0; i < 4; i++) {
        int f = i * 128 + tid;
        int r = f >> 3, c = (f & 7) * 16;
        cp_async16(sb + QH_OFF + r * ASTB + c, Qhg + r * 128 + c);
        cp_async16(sb + QL_OFF + r * ASTB + c, Qlg + r * 128 + c);
    }
    CP_COMMIT();

    auto load_kv = [&](int kt, int buf) {
        uint32_t base = sb + KV_OFF + buf * KVBUF;
        size_t go0 = (size_t)kt * 64 * 128;
        #pragma unroll
        for (int i = 0; i < 4; i++) {
            int f = i * 128 + tid;
            int r = f >> 3, c = (f & 7) * 16;
            uint32_t so = r * ASTB + c;
            size_t go = go0 + r * 128 + c;
            cp_async16(base + so,             Khg + go);
            cp_async16(base + TILE9 + so,     Klg + go);
            cp_async16(base + 2 * TILE9 + so, Vhg + go);
            cp_async16(base + 3 * TILE9 + so, Vlg + go);
        }
        CP_COMMIT();
    };

    load_kv(0, 0);
    CP_WAIT(1);
    __syncthreads();

    uint32_t qh[4][4], ql[4][4];
    const uint32_t a_off = (uint32_t)((wid * 16 + (lane & 15)) * ASTB + (lane >> 4) * 16);
    #pragma unroll
    for (int ks = 0; ks < 4; ks++) {
        ldsm_x4(qh[ks][0], qh[ks][1], qh[ks][2], qh[ks][3], sb + QH_OFF + a_off + ks * 32);
        ldsm_x4(ql[ks][0], ql[ks][1], ql[ks][2], ql[ks][3], sb + QL_OFF + a_off + ks * 32);
    }

    float o[8][4];
    #pragma unroll
    for (int nt = 0; nt < 8; nt++)
        #pragma unroll
        for (int c = 0; c < 4; c++) o[nt][c] = 0.f;
    float m0 = -1e30f, m1 = -1e30f, l0 = 0.f, l1 = 0.f;

    const uint32_t kb_off = (uint32_t)(((((lane >> 4) << 3) + (lane & 7))) * ASTB
                                       + ((lane >> 3) & 1) * 16);
    const uint32_t vt_off = (uint32_t)(((((lane >> 3) & 1) * 8 + (lane & 7))) * ASTB
                                       + (lane >> 4) * 16);

    const int nkt = qt + 1;
    for (int kt = 0; kt < nkt; kt++) {
        const int buf = kt & 1;
        if (kt + 1 < nkt) { load_kv(kt + 1, buf ^ 1); CP_WAIT(1); }
        else              { CP_WAIT(0); }
        __syncthreads();

        const uint32_t kvb = sb + KV_OFF + buf * KVBUF;

        float s[8][4];
        #pragma unroll
        for (int nt = 0; nt < 8; nt++)
            #pragma unroll
            for (int c = 0; c < 4; c++) s[nt][c] = 0.f;

        #pragma unroll
        for (int nt16 = 0; nt16 < 4; nt16++) {
            #pragma unroll
            for (int ks = 0; ks < 4; ks++) {
                uint32_t k0, k1, k2, k3, e0, e1, e2, e3;
                uint32_t addr = kvb + kb_off + nt16 * 16 * ASTB + ks * 32;
                ldsm_x4(k0, k1, k2, k3, addr);
                ldsm_x4(e0, e1, e2, e3, addr + TILE9);
                const int nA = nt16 * 2, nB = nA + 1;
                MMA4(s[nA], qh[ks], k0, k1);
                MMA4(s[nA], qh[ks], e0, e1);
                MMA4(s[nA], ql[ks], k0, k1);
                MMA4(s[nB], qh[ks], k2, k3);
                MMA4(s[nB], qh[ks], e2, e3);
                MMA4(s[nB], ql[ks], k2, k3);
            }
        }

        if (kt == qt) {
            const int qr = wid * 16 + (lane >> 2);
            #pragma unroll
            for (int nt = 0; nt < 8; nt++) {
                int j0 = nt * 8 + (lane & 3) * 2;
                if (j0     > qr)     s[nt][0] = -1e30f;
                if (j0 + 1 > qr)     s[nt][1] = -1e30f;
                if (j0     > qr + 8) s[nt][2] = -1e30f;
                if (j0 + 1 > qr + 8) s[nt][3] = -1e30f;
            }
        }

        float mx0 = -1e30f, mx1 = -1e30f;
        #pragma unroll
        for (int nt = 0; nt < 8; nt++) {
            mx0 = fmaxf(mx0, fmaxf(s[nt][0], s[nt][1]));
            mx1 = fmaxf(mx1, fmaxf(s[nt][2], s[nt][3]));
        }
        mx0 = fmaxf(mx0, __shfl_xor_sync(0xffffffffu, mx0, 1));
        mx0 = fmaxf(mx0, __shfl_xor_sync(0xffffffffu, mx0, 2));
        mx1 = fmaxf(mx1, __shfl_xor_sync(0xffffffffu, mx1, 1));
        mx1 = fmaxf(mx1, __shfl_xor_sync(0xffffffffu, mx1, 2));
        float mn0 = fmaxf(m0, mx0), mn1 = fmaxf(m1, mx1);
        float cr0 = __expf(m0 - mn0), cr1 = __expf(m1 - mn1);
        m0 = mn0; m1 = mn1;

        float t0 = 0.f, t1 = 0.f;
        #pragma unroll
        for (int nt = 0; nt < 8; nt++) {
            s[nt][0] = __expf(s[nt][0] - mn0); t0 += s[nt][0];
            s[nt][1] = __expf(s[nt][1] - mn0); t0 += s[nt][1];
            s[nt][2] = __expf(s[nt][2] - mn1); t1 += s[nt][2];
            s[nt][3] = __expf(s[nt][3] - mn1); t1 += s[nt][3];
        }
        t0 += __shfl_xor_sync(0xffffffffu, t0, 1);
        t0 += __shfl_xor_sync(0xffffffffu, t0, 2);
        t1 += __shfl_xor_sync(0xffffffffu, t1, 1);
        t1 += __shfl_xor_sync(0xffffffffu, t1, 2);
        l0 = l0 * cr0 + t0;
        l1 = l1 * cr1 + t1;
        #pragma unroll
        for (int nt = 0; nt < 8; nt++) {
            o[nt][0] *= cr0; o[nt][1] *= cr0;
            o[nt][2] *= cr1; o[nt][3] *= cr1;
        }

        uint32_t ph[4][4], pl[4][4];
        #pragma unroll
        for (int t = 0; t < 4; t++) {
            split2(s[2 * t][0],     s[2 * t][1],     ph[t][0], pl[t][0]);
            split2(s[2 * t][2],     s[2 * t][3],     ph[t][1], pl[t][1]);
            split2(s[2 * t + 1][0], s[2 * t + 1][1], ph[t][2], pl[t][2]);
            split2(s[2 * t + 1][2], s[2 * t + 1][3], ph[t][3], pl[t][3]);
        }

        #pragma unroll
        for (int g = 0; g < 4; g++) {
            #pragma unroll
            for (int t = 0; t < 4; t++) {
                uint32_t v0, v1, v2, v3, w0, w1, w2, w3;
                uint32_t addr = kvb + 2 * TILE9 + vt_off + t * 16 * ASTB + g * 32;
                ldsm_x4_t(v0, v1, v2, v3, addr);
                ldsm_x4_t(w0, w1, w2, w3, addr + TILE9);
                const int nA = g * 2, nB = nA + 1;
                MMA4(o[nA], ph[t], v0, v1);
                MMA4(o[nA], ph[t], w0, w1);
                MMA4(o[nA], pl[t], v0, v1);
                MMA4(o[nB], ph[t], v2, v3);
                MMA4(o[nB], ph[t], w2, w3);
                MMA4(o[nB], pl[t], v2, v3);
            }
        }
        __syncthreads();
    }

    float il0 = 1.f / l0, il1 = 1.f / l1;
    int trow = qt * 64 + wid * 16 + (lane >> 2);
    #pragma unroll
    for (int nt = 0; nt < 8; nt++) {
        int d = nt * 8 + (lane & 3) * 2;
        float2 u0 = make_float2(o[nt][0] * il0, o[nt][1] * il0);
        float2 u1 = make_float2(o[nt][2] * il1, o[nt][3] * il1);
        *(float2*)(out + ((size_t)(bb * SEQ + trow)     * EMB) + hh * 64 + d) = u0;
        *(float2*)(out + ((size_t)(bb * SEQ + trow + 8) * EMB) + hh * 64 + d) = u1;
    }
}

// ---------------------------------------------------------------------------
extern "C" void kernel_launch(void* const* d_in, const int* in_sizes, int n_in,
                              void* d_out, int out_size) {
    const float* x    = (const float*)d_in[0];
    const float* w    = (const float*)d_in[1];
    const float* bias = (const float*)d_in[2];
    float* out = (float*)d_out;

    split_x<<<M_TOT * K_TOT / (256 * 4), 256>>>(x);
    split_w<<<dim3(N_TOT / 32, K_TOT / 32), dim3(32, 8)>>>(w);

    const int gemm_smem = 2 * BUF_B;   // 122880 B
    cudaFuncSetAttribute(qkv_tc, cudaFuncAttributeMaxDynamicSharedMemorySize, gemm_smem);
    qkv_tc<<<dim3(N_TOT / 128, M_TOT / 256), 256, gemm_smem>>>(bias);

    const int attn_smem = 2 * TILE9 + 2 * KVBUF;   // 92160 B
    cudaFuncSetAttribute(attn_mma, cudaFuncAttributeMaxDynamicSharedMemorySize, attn_smem);
    attn_mma<<<dim3(SEQ / 64, NH, BATCH), 128, attn_smem>>>(out);
}

// round 6
// speedup vs baseline: 3.6836x; 1.1723x over previous
#include <cuda_runtime.h>
#include <cuda_bf16.h>
#include <cstdint>

#define BATCH 2
#define SEQ   2048
#define EMB   1024
#define NH    16
#define HD    64
#define M_TOT (BATCH*SEQ)   // 4096
#define N_TOT (3*EMB)       // 3072
#define K_TOT EMB           // 1024

// ---------------------------------------------------------------------------
// Device scratch (allocation-free)
// ---------------------------------------------------------------------------
__device__ __nv_bfloat16 g_qh[(size_t)BATCH*NH*SEQ*HD];
__device__ __nv_bfloat16 g_ql[(size_t)BATCH*NH*SEQ*HD];
__device__ __nv_bfloat16 g_kh[(size_t)BATCH*NH*SEQ*HD];
__device__ __nv_bfloat16 g_kl[(size_t)BATCH*NH*SEQ*HD];
__device__ __nv_bfloat16 g_vh[(size_t)BATCH*NH*SEQ*HD];
__device__ __nv_bfloat16 g_vl[(size_t)BATCH*NH*SEQ*HD];

__device__ __nv_bfloat16 g_xh[(size_t)M_TOT*K_TOT];
__device__ __nv_bfloat16 g_xl[(size_t)M_TOT*K_TOT];
__device__ __nv_bfloat16 g_wth[(size_t)N_TOT*K_TOT];   // W^T hi: [N,K]
__device__ __nv_bfloat16 g_wtl[(size_t)N_TOT*K_TOT];   // W^T lo: [N,K]

// ---------------------------------------------------------------------------
// Helpers
// ---------------------------------------------------------------------------
__device__ __forceinline__ uint32_t smem_u32(const void* p) {
    uint32_t a;
    asm("{ .reg .u64 t; cvta.to.shared.u64 t, %1; cvt.u32.u64 %0, t; }" : "=r"(a) : "l"(p));
    return a;
}

__device__ __forceinline__ void cp_async16(uint32_t s, const void* g) {
    asm volatile("cp.async.cg.shared.global [%0], [%1], 16;" :: "r"(s), "l"(g) : "memory");
}
#define CP_COMMIT() asm volatile("cp.async.commit_group;" ::: "memory")
#define CP_WAIT(n)  asm volatile("cp.async.wait_group %0;" :: "n"(n) : "memory")

__device__ __forceinline__ void ldsm_x4(uint32_t& r0, uint32_t& r1, uint32_t& r2,
                                        uint32_t& r3, uint32_t addr) {
    asm volatile("ldmatrix.sync.aligned.m8n8.x4.shared.b16 {%0,%1,%2,%3}, [%4];"
                 : "=r"(r0), "=r"(r1), "=r"(r2), "=r"(r3) : "r"(addr));
}

__device__ __forceinline__ void ldsm_x4_t(uint32_t& r0, uint32_t& r1, uint32_t& r2,
                                          uint32_t& r3, uint32_t addr) {
    asm volatile("ldmatrix.sync.aligned.m8n8.x4.trans.shared.b16 {%0,%1,%2,%3}, [%4];"
                 : "=r"(r0), "=r"(r1), "=r"(r2), "=r"(r3) : "r"(addr));
}

__device__ __forceinline__ void mma_16816(float& c0, float& c1, float& c2, float& c3,
                                          uint32_t a0, uint32_t a1, uint32_t a2, uint32_t a3,
                                          uint32_t b0, uint32_t b1) {
    asm volatile(
        "mma.sync.aligned.m16n8k16.row.col.f32.bf16.bf16.f32 "
        "{%0,%1,%2,%3}, {%4,%5,%6,%7}, {%8,%9}, {%0,%1,%2,%3};"
        : "+f"(c0), "+f"(c1), "+f"(c2), "+f"(c3)
        : "r"(a0), "r"(a1), "r"(a2), "r"(a3), "r"(b0), "r"(b1));
}
#define MMA4(S, A, B0, B1) \
    mma_16816((S)[0], (S)[1], (S)[2], (S)[3], (A)[0], (A)[1], (A)[2], (A)[3], (B0), (B1))

__device__ __forceinline__ void split2(float x, float y, uint32_t& hi, uint32_t& lo) {
    __nv_bfloat162 h2 = __floats2bfloat162_rn(x, y);
    __nv_bfloat162 l2 = __floats2bfloat162_rn(x - __bfloat162float(h2.x),
                                              y - __bfloat162float(h2.y));
    hi = *reinterpret_cast<uint32_t*>(&h2);
    lo = *reinterpret_cast<uint32_t*>(&l2);
}

// XOR swizzle for 128B-row tiles: r = row, c = 16B-chunk index (0..7)
#define SWZ(r, c) ((uint32_t)((r) * 128 + ((((c) ^ ((r) & 7))) << 4)))

// ---------------------------------------------------------------------------
// Split kernels
// ---------------------------------------------------------------------------
__global__ void split_x(const float* __restrict__ x) {
    int i = blockIdx.x * 256 + threadIdx.x;
    float4 v = ((const float4*)x)[i];
    __nv_bfloat16 h0 = __float2bfloat16(v.x);
    __nv_bfloat16 h1 = __float2bfloat16(v.y);
    __nv_bfloat16 h2 = __float2bfloat16(v.z);
    __nv_bfloat16 h3 = __float2bfloat16(v.w);
    __nv_bfloat16 l0 = __float2bfloat16(v.x - __bfloat162float(h0));
    __nv_bfloat16 l1 = __float2bfloat16(v.y - __bfloat162float(h1));
    __nv_bfloat16 l2 = __float2bfloat16(v.z - __bfloat162float(h2));
    __nv_bfloat16 l3 = __float2bfloat16(v.w - __bfloat162float(h3));
    ((__nv_bfloat162*)g_xh)[2 * i]     = __halves2bfloat162(h0, h1);
    ((__nv_bfloat162*)g_xh)[2 * i + 1] = __halves2bfloat162(h2, h3);
    ((__nv_bfloat162*)g_xl)[2 * i]     = __halves2bfloat162(l0, l1);
    ((__nv_bfloat162*)g_xl)[2 * i + 1] = __halves2bfloat162(l2, l3);
}

__global__ void split_w(const float* __restrict__ w) {
    __shared__ float t[32][33];
    int nb = blockIdx.x * 32, kb = blockIdx.y * 32;
    int tx = threadIdx.x, ty = threadIdx.y;      // (32, 8)
    #pragma unroll
    for (int r = ty; r < 32; r += 8)
        t[r][tx] = w[(size_t)(kb + r) * N_TOT + nb + tx];
    __syncthreads();
    #pragma unroll
    for (int r = ty; r < 32; r += 8) {
        float v = t[tx][r];
        __nv_bfloat16 h = __float2bfloat16(v);
        size_t idx = (size_t)(nb + r) * K_TOT + kb + tx;
        g_wth[idx] = h;
        g_wtl[idx] = __float2bfloat16(v - __bfloat162float(h));
    }
}

// ---------------------------------------------------------------------------
// HMMA QKV GEMM: CTA 256(M) x 128(N), 8 warps (64x64), k-chunk 64 (128B rows,
// XOR swizzle), double-buffered cp.async, MMA RAW-distance 8.
// ---------------------------------------------------------------------------
#define OFF_AH 0
#define OFF_AL 32768
#define OFF_BH 65536
#define OFF_BL 81920
#define BUF_B  98304

__global__ __launch_bounds__(256, 1) void qkv_tc(const float* __restrict__ bias) {
    extern __shared__ __align__(1024) char smem[];
    const uint32_t sbase = smem_u32(smem);
    const int tid  = threadIdx.x;
    const int lane = tid & 31;
    const int wid  = tid >> 5;
    const int wm   = wid >> 1;        // 0..3
    const int wn   = wid & 1;         // 0..1
    const int bnB  = blockIdx.x;      // 0..23
    const int bmB  = blockIdx.y;      // 0..15

    const __nv_bfloat16* Axh = g_xh  + (size_t)(bmB * 256) * K_TOT;
    const __nv_bfloat16* Axl = g_xl  + (size_t)(bmB * 256) * K_TOT;
    const __nv_bfloat16* Bwh = g_wth + (size_t)(bnB * 128) * K_TOT;
    const __nv_bfloat16* Bwl = g_wtl + (size_t)(bnB * 128) * K_TOT;

    auto load_tiles = [&](int ch, int buf) {
        uint32_t sb = sbase + buf * BUF_B;
        #pragma unroll
        for (int it = 0; it < 8; it++) {          // A: 256 rows x 128B
            int f = it * 256 + tid;
            int r = f >> 3, c = f & 7;
            size_t g = (size_t)r * K_TOT + ch * 64 + c * 8;
            uint32_t s = SWZ(r, c);
            cp_async16(sb + OFF_AH + s, Axh + g);
            cp_async16(sb + OFF_AL + s, Axl + g);
        }
        #pragma unroll
        for (int it = 0; it < 4; it++) {          // B: 128 rows x 128B
            int f = it * 256 + tid;
            int r = f >> 3, c = f & 7;
            size_t g = (size_t)r * K_TOT + ch * 64 + c * 8;
            uint32_t s = SWZ(r, c);
            cp_async16(sb + OFF_BH + s, Bwh + g);
            cp_async16(sb + OFF_BL + s, Bwl + g);
        }
        CP_COMMIT();
    };

    float acc[4][8][4];
    #pragma unroll
    for (int i = 0; i < 4; i++)
        #pragma unroll
        for (int j = 0; j < 8; j++)
            #pragma unroll
            for (int c = 0; c < 4; c++) acc[i][j][c] = 0.f;

    load_tiles(0, 0);

    const int NCH = K_TOT / 64;   // 16
    for (int ch = 0; ch < NCH; ch++) {
        const int buf = ch & 1;
        if (ch + 1 < NCH) { load_tiles(ch + 1, buf ^ 1); CP_WAIT(1); }
        else              { CP_WAIT(0); }
        __syncthreads();

        const uint32_t sbuf = sbase + buf * BUF_B;
        #pragma unroll
        for (int kh = 0; kh < 4; kh++) {
            uint32_t ah[4][4], al[4][4];
            #pragma unroll
            for (int am = 0; am < 4; am++) {
                int row = wm * 64 + am * 16 + (lane & 15);
                int chn = kh * 2 + (lane >> 4);
                uint32_t sw = SWZ(row, chn);
                ldsm_x4(ah[am][0], ah[am][1], ah[am][2], ah[am][3], sbuf + OFF_AH + sw);
                ldsm_x4(al[am][0], al[am][1], al[am][2], al[am][3], sbuf + OFF_AL + sw);
            }
            #pragma unroll
            for (int bp = 0; bp < 4; bp++) {
                int row = wn * 64 + bp * 16 + ((lane >> 4) << 3) + (lane & 7);
                int chn = kh * 2 + ((lane >> 3) & 1);
                uint32_t sw = SWZ(row, chn);
                uint32_t b0, b1, b2, b3, c0, c1, c2, c3;
                ldsm_x4(b0, b1, b2, b3, sbuf + OFF_BH + sw);
                ldsm_x4(c0, c1, c2, c3, sbuf + OFF_BL + sw);
                const int nA = bp * 2, nB = nA + 1;
                #pragma unroll
                for (int am = 0; am < 4; am++) MMA4(acc[am][nA], ah[am], b0, b1);
                #pragma unroll
                for (int am = 0; am < 4; am++) MMA4(acc[am][nB], ah[am], b2, b3);
                #pragma unroll
                for (int am = 0; am < 4; am++) MMA4(acc[am][nA], ah[am], c0, c1);
                #pragma unroll
                for (int am = 0; am < 4; am++) MMA4(acc[am][nB], ah[am], c2, c3);
                #pragma unroll
                for (int am = 0; am < 4; am++) MMA4(acc[am][nA], al[am], b0, b1);
                #pragma unroll
                for (int am = 0; am < 4; am++) MMA4(acc[am][nB], al[am], b2, b3);
            }
        }
        __syncthreads();
    }

    // Epilogue: bias, scale Q, split to bf16 hi/lo, scatter to [B,H,T,D]
    const int mq = lane >> 2;
    const int nq = (lane & 3) * 2;
    const int nbase = bnB * 128 + wn * 64;
    const int p = nbase >> 10;
    __nv_bfloat16 *dh, *dl;
    if (p == 0)      { dh = g_qh; dl = g_ql; }
    else if (p == 1) { dh = g_kh; dl = g_kl; }
    else             { dh = g_vh; dl = g_vl; }
    const float sc = (p == 0) ? 0.125f : 1.0f;

    #pragma unroll
    for (int bn = 0; bn < 8; bn++) {
        int n = nbase + bn * 8 + nq;
        float2 bb = *(const float2*)(bias + n);
        int cc = n & 1023;
        int hh = cc >> 6, d = cc & 63;
        #pragma unroll
        for (int am = 0; am < 4; am++) {
            #pragma unroll
            for (int half = 0; half < 2; half++) {
                int m = bmB * 256 + wm * 64 + am * 16 + mq + half * 8;
                int bi = m >> 11, t = m & 2047;
                float vx = (acc[am][bn][half * 2]     + bb.x) * sc;
                float vy = (acc[am][bn][half * 2 + 1] + bb.y) * sc;
                uint32_t hi, lo;
                split2(vx, vy, hi, lo);
                size_t idx = ((size_t)(bi * NH + hh) * SEQ + t) * HD + d;
                *(uint32_t*)(dh + idx) = hi;
                *(uint32_t*)(dl + idx) = lo;
            }
        }
    }
}

// ---------------------------------------------------------------------------
// Tensor-core flash attention, software-pipelined:
//   S(kt+1) MMAs issued BEFORE softmax(kt) so the tensor pipe stays busy.
// 3 K/V smem buffers (128B swizzled rows), loads issued 2 tiles ahead.
// CTA: 64 Q rows, 4 warps, 2 CTAs/SM.
// ---------------------------------------------------------------------------
#define KVT    8192             // one 64x64 bf16 plane, 128B rows
#define KVBUF3 (4 * KVT)        // Kh,Kl,Vh,Vl = 32768
#define KVOFF  16384            // after Qh (8192) + Ql (8192)
#define ATTN_SMEM (KVOFF + 3 * KVBUF3)   // 114688

__global__ __launch_bounds__(128, 2) void attn_mma(float* __restrict__ out) {
    extern __shared__ __align__(1024) char smem[];
    const uint32_t sb = smem_u32(smem);
    const int tid = threadIdx.x, lane = tid & 31, wid = tid >> 5;
    const int qt = blockIdx.x, hh = blockIdx.y, bb = blockIdx.z;

    const size_t head = (size_t)(bb * NH + hh) * SEQ * HD;
    const char* Qhg = (const char*)(g_qh + head + (size_t)qt * 64 * HD);
    const char* Qlg = (const char*)(g_ql + head + (size_t)qt * 64 * HD);
    const char* Khg = (const char*)(g_kh + head);
    const char* Klg = (const char*)(g_kl + head);
    const char* Vhg = (const char*)(g_vh + head);
    const char* Vlg = (const char*)(g_vl + head);

    // Q -> smem
    #pragma unroll
    for (int i = 0; i < 4; i++) {
        int f = i * 128 + tid;
        int r = f >> 3, c = f & 7;
        uint32_t sw = SWZ(r, c);
        cp_async16(sb + 0    + sw, Qhg + r * 128 + c * 16);
        cp_async16(sb + 8192 + sw, Qlg + r * 128 + c * 16);
    }
    CP_COMMIT();

    auto load_kv = [&](int kt, int buf) {
        uint32_t base = sb + KVOFF + buf * KVBUF3;
        size_t go0 = (size_t)kt * 64 * 128;
        #pragma unroll
        for (int i = 0; i < 4; i++) {
            int f = i * 128 + tid;
            int r = f >> 3, c = f & 7;
            uint32_t sw = SWZ(r, c);
            size_t go = go0 + r * 128 + c * 16;
            cp_async16(base + sw,           Khg + go);
            cp_async16(base + KVT + sw,     Klg + go);
            cp_async16(base + 2 * KVT + sw, Vhg + go);
            cp_async16(base + 3 * KVT + sw, Vlg + go);
        }
        CP_COMMIT();
    };

    const int nkt = qt + 1;
    load_kv(0, 0);
    if (nkt > 1) { load_kv(1, 1); CP_WAIT(1); }   // Q + kv0 done
    else         { CP_WAIT(0); }
    __syncthreads();

    // Q fragments (resident)
    uint32_t qh[4][4], ql[4][4];
    {
        int row = wid * 16 + (lane & 15);
        #pragma unroll
        for (int ks = 0; ks < 4; ks++) {
            int chn = ks * 2 + (lane >> 4);
            uint32_t sw = SWZ(row, chn);
            ldsm_x4(qh[ks][0], qh[ks][1], qh[ks][2], qh[ks][3], sb + 0    + sw);
            ldsm_x4(ql[ks][0], ql[ks][1], ql[ks][2], ql[ks][3], sb + 8192 + sw);
        }
    }

    // S-MMA issue for a K buffer
    auto issue_S = [&](int buf, float (*s)[4]) {
        uint32_t kbase = sb + KVOFF + buf * KVBUF3;
        #pragma unroll
        for (int nt16 = 0; nt16 < 4; nt16++) {
            int krow = nt16 * 16 + ((lane >> 4) << 3) + (lane & 7);
            #pragma unroll
            for (int ks = 0; ks < 4; ks++) {
                int chn = ks * 2 + ((lane >> 3) & 1);
                uint32_t sw = SWZ(krow, chn);
                uint32_t k0, k1, k2, k3, e0, e1, e2, e3;
                ldsm_x4(k0, k1, k2, k3, kbase + sw);          // Kh
                ldsm_x4(e0, e1, e2, e3, kbase + KVT + sw);    // Kl
                const int nA = nt16 * 2, nB = nA + 1;
                MMA4(s[nA], qh[ks], k0, k1);
                MMA4(s[nB], qh[ks], k2, k3);
                MMA4(s[nA], qh[ks], e0, e1);
                MMA4(s[nB], qh[ks], e2, e3);
                MMA4(s[nA], ql[ks], k0, k1);
                MMA4(s[nB], ql[ks], k2, k3);
            }
        }
    };

    float sA[8][4], sB[8][4];
    #pragma unroll
    for (int nt = 0; nt < 8; nt++)
        #pragma unroll
        for (int c = 0; c < 4; c++) sA[nt][c] = 0.f;
    issue_S(0, sA);

    float o[8][4];
    #pragma unroll
    for (int nt = 0; nt < 8; nt++)
        #pragma unroll
        for (int c = 0; c < 4; c++) o[nt][c] = 0.f;
    float m0 = -1e30f, m1 = -1e30f, l0 = 0.f, l1 = 0.f;

    for (int kt = 0; kt < nkt; kt++) {
        const int buf = kt - (kt / 3) * 3;          // kt % 3
        const bool has_next = (kt + 1 < nkt);

        if (kt + 2 < nkt) {
            load_kv(kt + 2, (kt + 2) % 3);
            CP_WAIT(1);                              // kv(kt+1) ready
        } else if (has_next) {
            CP_WAIT(0);
        }
        if (has_next) {
            __syncthreads();
            #pragma unroll
            for (int nt = 0; nt < 8; nt++)
                #pragma unroll
                for (int c = 0; c < 4; c++) sB[nt][c] = 0.f;
            issue_S((kt + 1) % 3, sB);               // tensor busy during softmax below
        }

        // ---- causal mask (diagonal tile) ----
        if (kt == qt) {
            const int qr = wid * 16 + (lane >> 2);
            #pragma unroll
            for (int nt = 0; nt < 8; nt++) {
                int j0 = nt * 8 + (lane & 3) * 2;
                if (j0     > qr)     sA[nt][0] = -1e30f;
                if (j0 + 1 > qr)     sA[nt][1] = -1e30f;
                if (j0     > qr + 8) sA[nt][2] = -1e30f;
                if (j0 + 1 > qr + 8) sA[nt][3] = -1e30f;
            }
        }

        // ---- online softmax (rows qr, qr+8) ----
        float mx0 = -1e30f, mx1 = -1e30f;
        #pragma unroll
        for (int nt = 0; nt < 8; nt++) {
            mx0 = fmaxf(mx0, fmaxf(sA[nt][0], sA[nt][1]));
            mx1 = fmaxf(mx1, fmaxf(sA[nt][2], sA[nt][3]));
        }
        mx0 = fmaxf(mx0, __shfl_xor_sync(0xffffffffu, mx0, 1));
        mx0 = fmaxf(mx0, __shfl_xor_sync(0xffffffffu, mx0, 2));
        mx1 = fmaxf(mx1, __shfl_xor_sync(0xffffffffu, mx1, 1));
        mx1 = fmaxf(mx1, __shfl_xor_sync(0xffffffffu, mx1, 2));
        float mn0 = fmaxf(m0, mx0), mn1 = fmaxf(m1, mx1);
        float cr0 = __expf(m0 - mn0), cr1 = __expf(m1 - mn1);
        m0 = mn0; m1 = mn1;

        float t0 = 0.f, t1 = 0.f;
        #pragma unroll
        for (int nt = 0; nt < 8; nt++) {
            sA[nt][0] = __expf(sA[nt][0] - mn0); t0 += sA[nt][0];
            sA[nt][1] = __expf(sA[nt][1] - mn0); t0 += sA[nt][1];
            sA[nt][2] = __expf(sA[nt][2] - mn1); t1 += sA[nt][2];
            sA[nt][3] = __expf(sA[nt][3] - mn1); t1 += sA[nt][3];
        }
        t0 += __shfl_xor_sync(0xffffffffu, t0, 1);
        t0 += __shfl_xor_sync(0xffffffffu, t0, 2);
        t1 += __shfl_xor_sync(0xffffffffu, t1, 1);
        t1 += __shfl_xor_sync(0xffffffffu, t1, 2);
        l0 = l0 * cr0 + t0;
        l1 = l1 * cr1 + t1;
        #pragma unroll
        for (int nt = 0; nt < 8; nt++) {
            o[nt][0] *= cr0; o[nt][1] *= cr0;
            o[nt][2] *= cr1; o[nt][3] *= cr1;
        }

        // ---- P -> bf16 hi/lo ----
        uint32_t ph[4][4], pl[4][4];
        #pragma unroll
        for (int t = 0; t < 4; t++) {
            split2(sA[2 * t][0],     sA[2 * t][1],     ph[t][0], pl[t][0]);
            split2(sA[2 * t][2],     sA[2 * t][3],     ph[t][1], pl[t][1]);
            split2(sA[2 * t + 1][0], sA[2 * t + 1][1], ph[t][2], pl[t][2]);
            split2(sA[2 * t + 1][2], sA[2 * t + 1][3], ph[t][3], pl[t][3]);
        }

        // ---- O += P V ----
        {
            uint32_t vbase = sb + KVOFF + buf * KVBUF3 + 2 * KVT;
            #pragma unroll
            for (int g = 0; g < 4; g++) {
                #pragma unroll
                for (int t = 0; t < 4; t++) {
                    int vrow = t * 16 + ((lane >> 3) & 1) * 8 + (lane & 7);
                    int chn = g * 2 + (lane >> 4);
                    uint32_t sw = SWZ(vrow, chn);
                    uint32_t v0, v1, v2, v3, w0, w1, w2, w3;
                    ldsm_x4_t(v0, v1, v2, v3, vbase + sw);          // Vh
                    ldsm_x4_t(w0, w1, w2, w3, vbase + KVT + sw);    // Vl
                    const int nA = g * 2, nB = nA + 1;
                    MMA4(o[nA], ph[t], v0, v1);
                    MMA4(o[nB], ph[t], v2, v3);
                    MMA4(o[nA], ph[t], w0, w1);
                    MMA4(o[nB], ph[t], w2, w3);
                    MMA4(o[nA], pl[t], v0, v1);
                    MMA4(o[nB], pl[t], v2, v3);
                }
            }
        }
        __syncthreads();   // all warps done reading this buffer

        if (has_next) {
            #pragma unroll
            for (int nt = 0; nt < 8; nt++)
                #pragma unroll
                for (int c = 0; c < 4; c++) sA[nt][c] = sB[nt][c];
        }
    }

    // ---- epilogue ----
    float il0 = 1.f / l0, il1 = 1.f / l1;
    int trow = qt * 64 + wid * 16 + (lane >> 2);
    #pragma unroll
    for (int nt = 0; nt < 8; nt++) {
        int d = nt * 8 + (lane & 3) * 2;
        float2 u0 = make_float2(o[nt][0] * il0, o[nt][1] * il0);
        float2 u1 = make_float2(o[nt][2] * il1, o[nt][3] * il1);
        *(float2*)(out + ((size_t)(bb * SEQ + trow)     * EMB) + hh * 64 + d) = u0;
        *(float2*)(out + ((size_t)(bb * SEQ + trow + 8) * EMB) + hh * 64 + d) = u1;
    }
}

// ---------------------------------------------------------------------------
extern "C" void kernel_launch(void* const* d_in, const int* in_sizes, int n_in,
                              void* d_out, int out_size) {
    const float* x    = (const float*)d_in[0];
    const float* w    = (const float*)d_in[1];
    const float* bias = (const float*)d_in[2];
    float* out = (float*)d_out;

    split_x<<<M_TOT * K_TOT / (256 * 4), 256>>>(x);
    split_w<<<dim3(N_TOT / 32, K_TOT / 32), dim3(32, 8)>>>(w);

    const int gemm_smem = 2 * BUF_B;   // 196608 B
    cudaFuncSetAttribute(qkv_tc, cudaFuncAttributeMaxDynamicSharedMemorySize, gemm_smem);
    qkv_tc<<<dim3(N_TOT / 128, M_TOT / 256), 256, gemm_smem>>>(bias);

    cudaFuncSetAttribute(attn_mma, cudaFuncAttributeMaxDynamicSharedMemorySize, ATTN_SMEM);
    attn_mma<<<dim3(SEQ / 64, NH, BATCH), 128, ATTN_SMEM>>>(out);
}